// round 12
// baseline (speedup 1.0000x reference)
#include <cuda_runtime.h>
#include <cuda_fp16.h>
#include <math.h>
#include <stdint.h>

// Problem dims
#define MB  4
#define MS  2048
#define MD  1024
#define MNH 16
#define MHD 64
#define MM  (MB * MS)   // 8192 rows

// ---------------- scratch (allocation-free: __device__ globals) ----------------
__device__ __half g_xh[MM * MD];
__device__ __half g_qh[MM * MD];
__device__ __half g_kh[MM * MD];
__device__ __half g_vh[MM * MD];
__device__ __half g_ch[MM * MD];
__device__ __half g_wt[4 * MD * MD];   // W^T per matrix: [N,K] K-major, fp16
__device__ float  g_msk[MB * MS];      // mask * log2(e)

// ======================= mma.sync helpers (sm_80+, no 'a'-gate) ===============
__device__ __forceinline__ uint32_t smem_to_u32(const void* p) {
    uint32_t a;
    asm("{ .reg .u64 t; cvta.to.shared.u64 t, %1; cvt.u32.u64 %0, t; }" : "=r"(a) : "l"(p));
    return a;
}

__device__ __forceinline__ void ldsm_x4(uint32_t* r, uint32_t addr) {
    asm volatile("ldmatrix.sync.aligned.m8n8.x4.shared.b16 {%0,%1,%2,%3}, [%4];"
                 : "=r"(r[0]), "=r"(r[1]), "=r"(r[2]), "=r"(r[3]) : "r"(addr));
}
__device__ __forceinline__ void ldsm_x4_t(uint32_t* r, uint32_t addr) {
    asm volatile("ldmatrix.sync.aligned.m8n8.x4.trans.shared.b16 {%0,%1,%2,%3}, [%4];"
                 : "=r"(r[0]), "=r"(r[1]), "=r"(r[2]), "=r"(r[3]) : "r"(addr));
}

__device__ __forceinline__ void mma_f16(float* d, const uint32_t* a, const uint32_t* b) {
    asm volatile(
        "mma.sync.aligned.m16n8k16.row.col.f32.f16.f16.f32 "
        "{%0,%1,%2,%3}, {%4,%5,%6,%7}, {%8,%9}, {%0,%1,%2,%3};"
        : "+f"(d[0]), "+f"(d[1]), "+f"(d[2]), "+f"(d[3])
        : "r"(a[0]), "r"(a[1]), "r"(a[2]), "r"(a[3]), "r"(b[0]), "r"(b[1]));
}

#define CP_ASYNC16(dst, src) \
    asm volatile("cp.async.cg.shared.global [%0], [%1], 16;" :: "r"(dst), "l"(src))
#define CP_COMMIT() asm volatile("cp.async.commit_group;")
#define CP_WAIT0()  asm volatile("cp.async.wait_group 0;")

__device__ __forceinline__ uint32_t pack_h2(float a, float b) {
    __half2 t(__float2half_rn(a), __float2half_rn(b));
    return *(uint32_t*)&t;
}

#define LOG2E 1.4426950408889634f

// ======================= prep kernels =======================
__global__ __launch_bounds__(256)
void cvt_h(const float* __restrict__ x, __half* __restrict__ h)
{
    int i = blockIdx.x * blockDim.x + threadIdx.x;
    float4 v = ((const float4*)x)[i];
    uint32_t* H = (uint32_t*)h;
    H[2*i]   = pack_h2(v.x, v.y);
    H[2*i+1] = pack_h2(v.z, v.w);
}

__global__ __launch_bounds__(256)
void scale_mask(const float* __restrict__ mask, float* __restrict__ msk)
{
    int i = blockIdx.x * blockDim.x + threadIdx.x;
    msk[i] = mask[i] * LOG2E;
}

__global__ __launch_bounds__(1024)
void transpose_cvt(const float* __restrict__ W0, const float* __restrict__ W1,
                   const float* __restrict__ W2, const float* __restrict__ W3,
                   __half* __restrict__ wt)
{
    __shared__ float t[32][33];
    int z = blockIdx.z;
    const float* src = (z == 0) ? W0 : (z == 1) ? W1 : (z == 2) ? W2 : W3;
    int k = blockIdx.y * 32 + threadIdx.y;
    int n = blockIdx.x * 32 + threadIdx.x;
    t[threadIdx.y][threadIdx.x] = src[k * MD + n];
    __syncthreads();
    int nn = blockIdx.x * 32 + threadIdx.y;
    int kk = blockIdx.y * 32 + threadIdx.x;
    wt[(size_t)z * MD * MD + (size_t)nn * MD + kk] = __float2half_rn(t[threadIdx.x][threadIdx.y]);
}

// ======================= mma.sync GEMM: plain fp16, BK=64 =====================
// C = A @ W + bias. Single fp16 operands. 128x128 tile, BK=64 (16 chunks),
// double-buffered register-prefetch, 1 MMA per fragment.
#define GBK 64
#define NCHK (MD / GBK)        // 16
#define SROW 72                // 64 + 8 pad (halfs); conflict-free for ldsm
#define BUF_E (128 * SROW)     // elems per stage buffer
#define SMEM_TOTAL (4 * BUF_E * 2)   // A[2] + B[2] stages, bytes = 73728

__global__ __launch_bounds__(256, 2)
void gemm_mma(const __half* __restrict__ A, const __half* __restrict__ Bt,
              const float* __restrict__ b0, const float* __restrict__ b1,
              const float* __restrict__ b2,
              float* __restrict__ Cf,
              __half* __restrict__ H0, __half* __restrict__ H1,
              __half* __restrict__ H2)
{
    extern __shared__ __half smem[];
    const int tid  = threadIdx.x;
    const int wid  = tid >> 5;
    const int lane = tid & 31;
    const int wm   = wid & 3;
    const int wn   = wid >> 2;

    const int z = blockIdx.z;
    const float* bias = (z == 0) ? b0 : (z == 1) ? b1 : b2;
    __half* Hout = (z == 0) ? H0 : (z == 1) ? H1 : H2;
    const __half* Bh = Bt + (size_t)z * MD * MD;

    const int n0 = blockIdx.x * 128;
    const int m0 = blockIdx.y * 128;

    __half* sA = smem;                  // [2][128][SROW]
    __half* sB = smem + 2 * BUF_E;

    // load geometry: 1024 chunks (16B) per buffer, 4 per thread
    int rr[4], cc_[4];
    #pragma unroll
    for (int j = 0; j < 4; j++) {
        int i = tid + j * 256;
        rr[j] = i >> 3;
        cc_[j] = (i & 7) << 3;
    }

    const uint32_t base_u32 = smem_to_u32(smem);
    const int a_r = wm * 32 + (lane & 15);
    const int a_c = (lane >> 4) << 3;
    const int b_r = wn * 64 + ((lane >> 4) << 3) + (lane & 7);
    const int b_c = ((lane >> 3) & 1) << 3;

    float acc[2][8][4];
    #pragma unroll
    for (int i = 0; i < 2; i++)
        #pragma unroll
        for (int j = 0; j < 8; j++)
            #pragma unroll
            for (int q = 0; q < 4; q++) acc[i][j][q] = 0.f;

    // prologue: chunk 0 into stage 0
    #pragma unroll
    for (int j = 0; j < 4; j++) {
        size_t gA = (size_t)(m0 + rr[j]) * MD + cc_[j];
        size_t gB = (size_t)(n0 + rr[j]) * MD + cc_[j];
        int so = rr[j] * SROW + cc_[j];
        *(uint4*)(sA + so) = *(const uint4*)(A + gA);
        *(uint4*)(sB + so) = *(const uint4*)(Bh + gB);
    }
    __syncthreads();

    for (int ch = 0; ch < NCHK; ch++) {
        const int cur = ch & 1;
        const int nxt = cur ^ 1;

        uint4 pA[4], pB[4];
        if (ch < NCHK - 1) {
            const int kc = (ch + 1) * GBK;
            #pragma unroll
            for (int j = 0; j < 4; j++) {
                pA[j] = *(const uint4*)(A + (size_t)(m0 + rr[j]) * MD + cc_[j] + kc);
                pB[j] = *(const uint4*)(Bh + (size_t)(n0 + rr[j]) * MD + cc_[j] + kc);
            }
        }

        const uint32_t stA = base_u32 + (uint32_t)(cur * BUF_E) * 2;
        #pragma unroll
        for (int ks = 0; ks < 4; ks++) {
            uint32_t ah[2][4], bb[4][4];
            const int kcol = ks * 16;
            #pragma unroll
            for (int mf = 0; mf < 2; mf++) {
                uint32_t off = (uint32_t)((a_r + mf * 16) * SROW + a_c + kcol) * 2;
                ldsm_x4(ah[mf], stA + off);
            }
            #pragma unroll
            for (int nf2 = 0; nf2 < 4; nf2++) {
                uint32_t off = (uint32_t)((b_r + nf2 * 16) * SROW + b_c + kcol) * 2;
                ldsm_x4(bb[nf2], stA + (uint32_t)(2 * BUF_E) * 2 + off);
            }
            #pragma unroll
            for (int mf = 0; mf < 2; mf++)
                #pragma unroll
                for (int nf = 0; nf < 8; nf++)
                    mma_f16(acc[mf][nf], ah[mf], &bb[nf >> 1][(nf & 1) * 2]);
        }

        if (ch < NCHK - 1) {
            __half* dA = sA + nxt * BUF_E;
            __half* dB = sB + nxt * BUF_E;
            #pragma unroll
            for (int j = 0; j < 4; j++) {
                int so = rr[j] * SROW + cc_[j];
                *(uint4*)(dA + so) = pA[j];
                *(uint4*)(dB + so) = pB[j];
            }
        }
        __syncthreads();
    }

    const int tq = lane >> 2;
    const int tr = lane & 3;
    #pragma unroll
    for (int mf = 0; mf < 2; mf++) {
        #pragma unroll
        for (int nf = 0; nf < 8; nf++) {
            const int n = n0 + wn * 64 + nf * 8 + tr * 2;
            const float bv0 = bias[n], bv1 = bias[n + 1];
            const int m_top = m0 + wm * 32 + mf * 16 + tq;
            float v0 = acc[mf][nf][0] + bv0, v1 = acc[mf][nf][1] + bv1;
            float v2 = acc[mf][nf][2] + bv0, v3 = acc[mf][nf][3] + bv1;
            if (Hout) {
                *(uint32_t*)(Hout + (size_t)m_top * MD + n)       = pack_h2(v0, v1);
                *(uint32_t*)(Hout + (size_t)(m_top + 8) * MD + n) = pack_h2(v2, v3);
            } else {
                float2 w0, w1;
                w0.x = v0; w0.y = v1;
                w1.x = v2; w1.y = v3;
                *(float2*)(Cf + (size_t)m_top * MD + n)       = w0;
                *(float2*)(Cf + (size_t)(m_top + 8) * MD + n) = w1;
            }
        }
    }
}

// ======================= flash attention (R11 structure, pre-scaled mask) =====
#define SR2 72
#define QBUF (128 * SR2)
#define KVT 64
#define KBUF (KVT * SR2)
#define ATT_SMEM ((QBUF + 4 * KBUF) * 2)   // 55296 bytes

__global__ __launch_bounds__(256, 2)
void attn_mma(const float* __restrict__ msk, __half* __restrict__ ctx)
{
    extern __shared__ __half sm[];   // [Q][stage][K|V]
    __shared__ float ms[2][KVT];

    const int tid  = threadIdx.x;
    const int wid  = tid >> 5;
    const int lane = tid & 31;
    const int bh   = blockIdx.y;
    const int b    = bh >> 4;
    const int h    = bh & 15;
    const int q0   = blockIdx.x * 128;

    const uint32_t sbase = smem_to_u32(sm);
    const uint32_t kvb   = sbase + (uint32_t)QBUF * 2;

    // ---- load Q tile (128x64) into resident smem ----
    #pragma unroll
    for (int it = 0; it < 4; it++) {
        int i = tid + it * 256;
        int r = i >> 3, c = (i & 7) << 3;
        size_t g = (size_t)(b * MS + q0 + r) * MD + h * 64 + c;
        *(uint4*)&sm[r * SR2 + c] = *(const uint4*)(g_qh + g);
    }

    const int cr0 = (tid + 0)   >> 3, cc0 = ((tid + 0)   & 7) << 3;
    const int cr1 = (tid + 256) >> 3, cc1 = ((tid + 256) & 7) << 3;
    const uint32_t d0 = (uint32_t)(cr0 * SR2 + cc0) * 2;
    const uint32_t d1 = (uint32_t)(cr1 * SR2 + cc1) * 2;
    const uint32_t msb = smem_to_u32(ms);

    const int a_r = wid * 16 + (lane & 15);
    const int a_c = (lane >> 4) << 3;
    const int b_r = ((lane >> 4) << 3) + (lane & 7);
    const int b_c = ((lane >> 3) & 1) << 3;
    const int v_r = (((lane >> 3) & 1) << 3) + (lane & 7);
    const int v_c = (lane >> 4) << 3;
    const int cq  = (lane & 3) * 2;

    float l0 = 0.f, l1 = 0.f;
    float o[8][4];
    #pragma unroll
    for (int nf = 0; nf < 8; nf++)
        #pragma unroll
        for (int q = 0; q < 4; q++) o[nf][q] = 0.f;

    // ---- prologue ----
    {
        size_t g0 = (size_t)(b * MS + cr0) * MD + h * 64 + cc0;
        size_t g1 = (size_t)(b * MS + cr1) * MD + h * 64 + cc1;
        CP_ASYNC16(kvb + 0 * KBUF * 2 + d0, g_kh + g0);
        CP_ASYNC16(kvb + 0 * KBUF * 2 + d1, g_kh + g1);
        CP_ASYNC16(kvb + 1 * KBUF * 2 + d0, g_vh + g0);
        CP_ASYNC16(kvb + 1 * KBUF * 2 + d1, g_vh + g1);
        if (tid < 16)
            CP_ASYNC16(msb + tid * 16, msk + b * MS + tid * 4);
        CP_COMMIT();
    }

    for (int kt = 0; kt < MS / KVT; kt++) {
        const int cur = kt & 1;
        CP_WAIT0();
        __syncthreads();

        if (kt < MS / KVT - 1) {
            const uint32_t stN = kvb + (uint32_t)((cur ^ 1) * 2 * KBUF) * 2;
            size_t g0 = (size_t)(b * MS + (kt + 1) * KVT + cr0) * MD + h * 64 + cc0;
            size_t g1 = (size_t)(b * MS + (kt + 1) * KVT + cr1) * MD + h * 64 + cc1;
            CP_ASYNC16(stN + 0 * KBUF * 2 + d0, g_kh + g0);
            CP_ASYNC16(stN + 0 * KBUF * 2 + d1, g_kh + g1);
            CP_ASYNC16(stN + 1 * KBUF * 2 + d0, g_vh + g0);
            CP_ASYNC16(stN + 1 * KBUF * 2 + d1, g_vh + g1);
            if (tid < 16)
                CP_ASYNC16(msb + (cur ^ 1) * 256 + tid * 16,
                           msk + b * MS + (kt + 1) * KVT + tid * 4);
            CP_COMMIT();
        }

        const uint32_t stC = kvb + (uint32_t)(cur * 2 * KBUF) * 2;

        // ---- S = Q K^T ----
        float s[8][4];
        #pragma unroll
        for (int nf = 0; nf < 8; nf++)
            #pragma unroll
            for (int q = 0; q < 4; q++) s[nf][q] = 0.f;

        #pragma unroll
        for (int ks = 0; ks < 4; ks++) {
            uint32_t qh4[4], kk[4][4];
            uint32_t qoff = (uint32_t)(a_r * SR2 + a_c + ks * 16) * 2;
            ldsm_x4(qh4, sbase + qoff);
            #pragma unroll
            for (int nf2 = 0; nf2 < 4; nf2++) {
                uint32_t off = (uint32_t)((b_r + nf2 * 16) * SR2 + b_c + ks * 16) * 2;
                ldsm_x4(kk[nf2], stC + 0 * KBUF * 2 + off);
            }
            #pragma unroll
            for (int nf = 0; nf < 8; nf++)
                mma_f16(s[nf], qh4, &kk[nf >> 1][(nf & 1) * 2]);
        }

        // ---- p = exp2(s*scale + msk); accumulate l ----
        #pragma unroll
        for (int nf = 0; nf < 8; nf++) {
            float ma = ms[cur][nf * 8 + cq];
            float mb = ms[cur][nf * 8 + cq + 1];
            s[nf][0] = exp2f(fmaf(s[nf][0], 0.125f * LOG2E, ma));
            s[nf][1] = exp2f(fmaf(s[nf][1], 0.125f * LOG2E, mb));
            s[nf][2] = exp2f(fmaf(s[nf][2], 0.125f * LOG2E, ma));
            s[nf][3] = exp2f(fmaf(s[nf][3], 0.125f * LOG2E, mb));
            l0 += s[nf][0] + s[nf][1];
            l1 += s[nf][2] + s[nf][3];
        }

        // ---- repack P -> A-fragments (single fp16) ----
        uint32_t ph[4][4];
        #pragma unroll
        for (int kf = 0; kf < 4; kf++) {
            ph[kf][0] = pack_h2(s[2*kf][0],   s[2*kf][1]);
            ph[kf][1] = pack_h2(s[2*kf][2],   s[2*kf][3]);
            ph[kf][2] = pack_h2(s[2*kf+1][0], s[2*kf+1][1]);
            ph[kf][3] = pack_h2(s[2*kf+1][2], s[2*kf+1][3]);
        }

        // ---- O += P V ----
        #pragma unroll
        for (int ks = 0; ks < 4; ks++) {
            uint32_t vv[4][4];
            #pragma unroll
            for (int nf2 = 0; nf2 < 4; nf2++) {
                uint32_t off = (uint32_t)((ks * 16 + v_r) * SR2 + nf2 * 16 + v_c) * 2;
                ldsm_x4_t(vv[nf2], stC + 1 * KBUF * 2 + off);
            }
            #pragma unroll
            for (int nf = 0; nf < 8; nf++)
                mma_f16(o[nf], ph[ks], &vv[nf >> 1][(nf & 1) * 2]);
        }
        __syncthreads();
    }

    // ---- finalize ----
    l0 += __shfl_xor_sync(0xffffffffu, l0, 1);
    l0 += __shfl_xor_sync(0xffffffffu, l0, 2);
    l1 += __shfl_xor_sync(0xffffffffu, l1, 1);
    l1 += __shfl_xor_sync(0xffffffffu, l1, 2);
    float i0 = 1.f / l0, i1 = 1.f / l1;
    const int r0 = lane >> 2;
    const size_t mrow = (size_t)(b * MS + q0 + wid * 16 + r0);
    #pragma unroll
    for (int nf = 0; nf < 8; nf++) {
        int d = h * 64 + nf * 8 + cq;
        *(uint32_t*)(ctx + mrow * MD + d)       = pack_h2(o[nf][0] * i0, o[nf][1] * i0);
        *(uint32_t*)(ctx + (mrow + 8) * MD + d) = pack_h2(o[nf][2] * i1, o[nf][3] * i1);
    }
}

// ---------------- launch ----------------
extern "C" void kernel_launch(void* const* d_in, const int* in_sizes, int n_in,
                              void* d_out, int out_size)
{
    const float* x    = (const float*)d_in[0];
    const float* mask = (const float*)d_in[1];
    const float* Wq   = (const float*)d_in[2];
    const float* bq   = (const float*)d_in[3];
    const float* Wk   = (const float*)d_in[4];
    const float* bk   = (const float*)d_in[5];
    const float* Wv   = (const float*)d_in[6];
    const float* bv   = (const float*)d_in[7];
    const float* Wo   = (const float*)d_in[8];
    const float* bo   = (const float*)d_in[9];
    float* out = (float*)d_out;

    __half *pxh, *pqh, *pkh, *pvh, *pch, *pwt;
    float* pmsk;
    cudaGetSymbolAddress((void**)&pxh,  g_xh);
    cudaGetSymbolAddress((void**)&pqh,  g_qh);
    cudaGetSymbolAddress((void**)&pkh,  g_kh);
    cudaGetSymbolAddress((void**)&pvh,  g_vh);
    cudaGetSymbolAddress((void**)&pch,  g_ch);
    cudaGetSymbolAddress((void**)&pwt,  g_wt);
    cudaGetSymbolAddress((void**)&pmsk, g_msk);

    cudaFuncSetAttribute(gemm_mma, cudaFuncAttributeMaxDynamicSharedMemorySize, SMEM_TOTAL);
    cudaFuncSetAttribute(attn_mma, cudaFuncAttributeMaxDynamicSharedMemorySize, ATT_SMEM);

    // 0) prep: x -> fp16; mask pre-scale; transpose+round weights to fp16
    cvt_h<<<(MM * MD / 4) / 256, 256>>>(x, pxh);
    scale_mask<<<(MB * MS) / 256, 256>>>(mask, pmsk);
    dim3 gt(MD / 32, MD / 32, 4);
    transpose_cvt<<<gt, dim3(32, 32)>>>(Wq, Wk, Wv, Wo, pwt);

    // 1) fused QKV projections -> fp16
    dim3 gqkv(MD / 128, MM / 128, 3);
    gemm_mma<<<gqkv, 256, SMEM_TOTAL>>>(pxh, pwt, bq, bk, bv, nullptr,
                                        pqh, pkh, pvh);

    // 2) flash attention -> ctx fp16
    dim3 gattn(MS / 128, MB * MNH);
    attn_mma<<<gattn, 256, ATT_SMEM>>>(pmsk, pch);

    // 3) O projection -> fp32 out
    dim3 go(MD / 128, MM / 128, 1);
    gemm_mma<<<go, 256, SMEM_TOTAL>>>(pch, pwt + 3 * (size_t)MD * MD,
                                      bo, bo, bo, out,
                                      nullptr, nullptr, nullptr);
}

// round 13
// speedup vs baseline: 1.3852x; 1.3852x over previous
#include <cuda_runtime.h>
#include <cuda_fp16.h>
#include <math.h>
#include <stdint.h>

// Problem dims
#define MB  4
#define MS  2048
#define MD  1024
#define MNH 16
#define MHD 64
#define MM  (MB * MS)   // 8192 rows

// ---------------- scratch (allocation-free: __device__ globals) ----------------
__device__ __half g_xh[MM * MD];
__device__ __half g_qh[MM * MD];
__device__ __half g_kh[MM * MD];
__device__ __half g_vh[MM * MD];
__device__ __half g_ch[MM * MD];
__device__ __half g_wt[4 * MD * MD];   // W^T per matrix: [N,K] K-major, fp16
__device__ float  g_msk[MB * MS];      // mask * log2(e)

// ======================= mma.sync helpers (sm_80+, no 'a'-gate) ===============
__device__ __forceinline__ uint32_t smem_to_u32(const void* p) {
    uint32_t a;
    asm("{ .reg .u64 t; cvta.to.shared.u64 t, %1; cvt.u32.u64 %0, t; }" : "=r"(a) : "l"(p));
    return a;
}

__device__ __forceinline__ void ldsm_x4(uint32_t* r, uint32_t addr) {
    asm volatile("ldmatrix.sync.aligned.m8n8.x4.shared.b16 {%0,%1,%2,%3}, [%4];"
                 : "=r"(r[0]), "=r"(r[1]), "=r"(r[2]), "=r"(r[3]) : "r"(addr));
}
__device__ __forceinline__ void ldsm_x4_t(uint32_t* r, uint32_t addr) {
    asm volatile("ldmatrix.sync.aligned.m8n8.x4.trans.shared.b16 {%0,%1,%2,%3}, [%4];"
                 : "=r"(r[0]), "=r"(r[1]), "=r"(r[2]), "=r"(r[3]) : "r"(addr));
}

__device__ __forceinline__ void mma_f16(float* d, const uint32_t* a, const uint32_t* b) {
    asm volatile(
        "mma.sync.aligned.m16n8k16.row.col.f32.f16.f16.f32 "
        "{%0,%1,%2,%3}, {%4,%5,%6,%7}, {%8,%9}, {%0,%1,%2,%3};"
        : "+f"(d[0]), "+f"(d[1]), "+f"(d[2]), "+f"(d[3])
        : "r"(a[0]), "r"(a[1]), "r"(a[2]), "r"(a[3]), "r"(b[0]), "r"(b[1]));
}

#define CP_ASYNC16(dst, src) \
    asm volatile("cp.async.cg.shared.global [%0], [%1], 16;" :: "r"(dst), "l"(src))
#define CP_COMMIT() asm volatile("cp.async.commit_group;")
#define CP_WAIT0()  asm volatile("cp.async.wait_group 0;")

__device__ __forceinline__ uint32_t pack_h2(float a, float b) {
    __half2 t(__float2half_rn(a), __float2half_rn(b));
    return *(uint32_t*)&t;
}

#define LOG2E 1.4426950408889634f

// ======================= prep kernels =======================
__global__ __launch_bounds__(256)
void cvt_h(const float* __restrict__ x, __half* __restrict__ h)
{
    int i = blockIdx.x * blockDim.x + threadIdx.x;
    float4 v = ((const float4*)x)[i];
    uint32_t* H = (uint32_t*)h;
    H[2*i]   = pack_h2(v.x, v.y);
    H[2*i+1] = pack_h2(v.z, v.w);
}

__global__ __launch_bounds__(256)
void scale_mask(const float* __restrict__ mask, float* __restrict__ msk)
{
    int i = blockIdx.x * blockDim.x + threadIdx.x;
    msk[i] = mask[i] * LOG2E;
}

__global__ __launch_bounds__(1024)
void transpose_cvt(const float* __restrict__ W0, const float* __restrict__ W1,
                   const float* __restrict__ W2, const float* __restrict__ W3,
                   __half* __restrict__ wt)
{
    __shared__ float t[32][33];
    int z = blockIdx.z;
    const float* src = (z == 0) ? W0 : (z == 1) ? W1 : (z == 2) ? W2 : W3;
    int k = blockIdx.y * 32 + threadIdx.y;
    int n = blockIdx.x * 32 + threadIdx.x;
    t[threadIdx.y][threadIdx.x] = src[k * MD + n];
    __syncthreads();
    int nn = blockIdx.x * 32 + threadIdx.y;
    int kk = blockIdx.y * 32 + threadIdx.x;
    wt[(size_t)z * MD * MD + (size_t)nn * MD + kk] = __float2half_rn(t[threadIdx.x][threadIdx.y]);
}

// ======================= mma.sync GEMM: plain fp16, BK=32 (R11 known-best) ====
#define GBK 32
#define NCHK (MD / GBK)        // 32
#define SROW 40                // 32 + 8 pad
#define BUF_E (128 * SROW)
#define SMEM_TOTAL (4 * BUF_E * 2)   // 40960 bytes

__global__ __launch_bounds__(256, 2)
void gemm_mma(const __half* __restrict__ A, const __half* __restrict__ Bt,
              const float* __restrict__ b0, const float* __restrict__ b1,
              const float* __restrict__ b2,
              float* __restrict__ Cf,
              __half* __restrict__ H0, __half* __restrict__ H1,
              __half* __restrict__ H2)
{
    extern __shared__ __half smem[];
    const int tid  = threadIdx.x;
    const int wid  = tid >> 5;
    const int lane = tid & 31;
    const int wm   = wid & 3;
    const int wn   = wid >> 2;

    const int z = blockIdx.z;
    const float* bias = (z == 0) ? b0 : (z == 1) ? b1 : b2;
    __half* Hout = (z == 0) ? H0 : (z == 1) ? H1 : H2;
    const __half* Bh = Bt + (size_t)z * MD * MD;

    const int n0 = blockIdx.x * 128;
    const int m0 = blockIdx.y * 128;

    __half* sA = smem;                  // [2][128][SROW]
    __half* sB = smem + 2 * BUF_E;

    int r0g = (tid + 0)   >> 2, c0g = ((tid + 0)   & 3) << 3;
    int r1g = (tid + 256) >> 2, c1g = ((tid + 256) & 3) << 3;
    const size_t gA0 = (size_t)(m0 + r0g) * MD + c0g;
    const size_t gA1 = (size_t)(m0 + r1g) * MD + c1g;
    const size_t gB0 = (size_t)(n0 + r0g) * MD + c0g;
    const size_t gB1 = (size_t)(n0 + r1g) * MD + c1g;
    const int s0 = r0g * SROW + c0g;
    const int s1 = r1g * SROW + c1g;

    const uint32_t base_u32 = smem_to_u32(smem);
    const int a_r = wm * 32 + (lane & 15);
    const int a_c = (lane >> 4) << 3;
    const int b_r = wn * 64 + ((lane >> 4) << 3) + (lane & 7);
    const int b_c = ((lane >> 3) & 1) << 3;

    float acc[2][8][4];
    #pragma unroll
    for (int i = 0; i < 2; i++)
        #pragma unroll
        for (int j = 0; j < 8; j++)
            #pragma unroll
            for (int q = 0; q < 4; q++) acc[i][j][q] = 0.f;

    {
        *(uint4*)(sA + s0) = *(const uint4*)(A + gA0);
        *(uint4*)(sA + s1) = *(const uint4*)(A + gA1);
        *(uint4*)(sB + s0) = *(const uint4*)(Bh + gB0);
        *(uint4*)(sB + s1) = *(const uint4*)(Bh + gB1);
    }
    __syncthreads();

    for (int ch = 0; ch < NCHK; ch++) {
        const int cur = ch & 1;
        const int nxt = cur ^ 1;

        uint4 pA0, pA1, pB0, pB1;
        if (ch < NCHK - 1) {
            const int kc = (ch + 1) * GBK;
            pA0 = *(const uint4*)(A + gA0 + kc);
            pA1 = *(const uint4*)(A + gA1 + kc);
            pB0 = *(const uint4*)(Bh + gB0 + kc);
            pB1 = *(const uint4*)(Bh + gB1 + kc);
        }

        const uint32_t stA = base_u32 + (uint32_t)(cur * BUF_E) * 2;
        #pragma unroll
        for (int ks = 0; ks < 2; ks++) {
            uint32_t ah[2][4], bb[4][4];
            const int kcol = ks * 16;
            #pragma unroll
            for (int mf = 0; mf < 2; mf++) {
                uint32_t off = (uint32_t)((a_r + mf * 16) * SROW + a_c + kcol) * 2;
                ldsm_x4(ah[mf], stA + off);
            }
            #pragma unroll
            for (int nf2 = 0; nf2 < 4; nf2++) {
                uint32_t off = (uint32_t)((b_r + nf2 * 16) * SROW + b_c + kcol) * 2;
                ldsm_x4(bb[nf2], stA + (uint32_t)(2 * BUF_E) * 2 + off);
            }
            #pragma unroll
            for (int mf = 0; mf < 2; mf++)
                #pragma unroll
                for (int nf = 0; nf < 8; nf++)
                    mma_f16(acc[mf][nf], ah[mf], &bb[nf >> 1][(nf & 1) * 2]);
        }

        if (ch < NCHK - 1) {
            __half* dA = sA + nxt * BUF_E;
            __half* dB = sB + nxt * BUF_E;
            *(uint4*)(dA + s0) = pA0;  *(uint4*)(dA + s1) = pA1;
            *(uint4*)(dB + s0) = pB0;  *(uint4*)(dB + s1) = pB1;
        }
        __syncthreads();
    }

    const int tq = lane >> 2;
    const int tr = lane & 3;
    #pragma unroll
    for (int mf = 0; mf < 2; mf++) {
        #pragma unroll
        for (int nf = 0; nf < 8; nf++) {
            const int n = n0 + wn * 64 + nf * 8 + tr * 2;
            const float bv0 = bias[n], bv1 = bias[n + 1];
            const int m_top = m0 + wm * 32 + mf * 16 + tq;
            float v0 = acc[mf][nf][0] + bv0, v1 = acc[mf][nf][1] + bv1;
            float v2 = acc[mf][nf][2] + bv0, v3 = acc[mf][nf][3] + bv1;
            if (Hout) {
                *(uint32_t*)(Hout + (size_t)m_top * MD + n)       = pack_h2(v0, v1);
                *(uint32_t*)(Hout + (size_t)(m_top + 8) * MD + n) = pack_h2(v2, v3);
            } else {
                float2 w0, w1;
                w0.x = v0; w0.y = v1;
                w1.x = v2; w1.y = v3;
                *(float2*)(Cf + (size_t)m_top * MD + n)       = w0;
                *(float2*)(Cf + (size_t)(m_top + 8) * MD + n) = w1;
            }
        }
    }
}

// ======================= flash attention (pre-scaled mask) ====================
#define SR2 72
#define QBUF (128 * SR2)
#define KVT 64
#define KBUF (KVT * SR2)
#define ATT_SMEM ((QBUF + 4 * KBUF) * 2)   // 55296 bytes

__global__ __launch_bounds__(256, 2)
void attn_mma(const float* __restrict__ msk, __half* __restrict__ ctx)
{
    extern __shared__ __half sm[];   // [Q][stage][K|V]
    __shared__ float ms[2][KVT];

    const int tid  = threadIdx.x;
    const int wid  = tid >> 5;
    const int lane = tid & 31;
    const int bh   = blockIdx.y;
    const int b    = bh >> 4;
    const int h    = bh & 15;
    const int q0   = blockIdx.x * 128;

    const uint32_t sbase = smem_to_u32(sm);
    const uint32_t kvb   = sbase + (uint32_t)QBUF * 2;

    // ---- load Q tile (128x64) into resident smem ----
    #pragma unroll
    for (int it = 0; it < 4; it++) {
        int i = tid + it * 256;
        int r = i >> 3, c = (i & 7) << 3;
        size_t g = (size_t)(b * MS + q0 + r) * MD + h * 64 + c;
        *(uint4*)&sm[r * SR2 + c] = *(const uint4*)(g_qh + g);
    }

    const int cr0 = (tid + 0)   >> 3, cc0 = ((tid + 0)   & 7) << 3;
    const int cr1 = (tid + 256) >> 3, cc1 = ((tid + 256) & 7) << 3;
    const uint32_t d0 = (uint32_t)(cr0 * SR2 + cc0) * 2;
    const uint32_t d1 = (uint32_t)(cr1 * SR2 + cc1) * 2;
    const uint32_t msb = smem_to_u32(ms);

    const int a_r = wid * 16 + (lane & 15);
    const int a_c = (lane >> 4) << 3;
    const int b_r = ((lane >> 4) << 3) + (lane & 7);
    const int b_c = ((lane >> 3) & 1) << 3;
    const int v_r = (((lane >> 3) & 1) << 3) + (lane & 7);
    const int v_c = (lane >> 4) << 3;
    const int cq  = (lane & 3) * 2;

    float l0 = 0.f, l1 = 0.f;
    float o[8][4];
    #pragma unroll
    for (int nf = 0; nf < 8; nf++)
        #pragma unroll
        for (int q = 0; q < 4; q++) o[nf][q] = 0.f;

    // ---- prologue ----
    {
        size_t g0 = (size_t)(b * MS + cr0) * MD + h * 64 + cc0;
        size_t g1 = (size_t)(b * MS + cr1) * MD + h * 64 + cc1;
        CP_ASYNC16(kvb + 0 * KBUF * 2 + d0, g_kh + g0);
        CP_ASYNC16(kvb + 0 * KBUF * 2 + d1, g_kh + g1);
        CP_ASYNC16(kvb + 1 * KBUF * 2 + d0, g_vh + g0);
        CP_ASYNC16(kvb + 1 * KBUF * 2 + d1, g_vh + g1);
        if (tid < 16)
            CP_ASYNC16(msb + tid * 16, msk + b * MS + tid * 4);
        CP_COMMIT();
    }

    for (int kt = 0; kt < MS / KVT; kt++) {
        const int cur = kt & 1;
        CP_WAIT0();
        __syncthreads();

        if (kt < MS / KVT - 1) {
            const uint32_t stN = kvb + (uint32_t)((cur ^ 1) * 2 * KBUF) * 2;
            size_t g0 = (size_t)(b * MS + (kt + 1) * KVT + cr0) * MD + h * 64 + cc0;
            size_t g1 = (size_t)(b * MS + (kt + 1) * KVT + cr1) * MD + h * 64 + cc1;
            CP_ASYNC16(stN + 0 * KBUF * 2 + d0, g_kh + g0);
            CP_ASYNC16(stN + 0 * KBUF * 2 + d1, g_kh + g1);
            CP_ASYNC16(stN + 1 * KBUF * 2 + d0, g_vh + g0);
            CP_ASYNC16(stN + 1 * KBUF * 2 + d1, g_vh + g1);
            if (tid < 16)
                CP_ASYNC16(msb + (cur ^ 1) * 256 + tid * 16,
                           msk + b * MS + (kt + 1) * KVT + tid * 4);
            CP_COMMIT();
        }

        const uint32_t stC = kvb + (uint32_t)(cur * 2 * KBUF) * 2;

        // ---- S = Q K^T ----
        float s[8][4];
        #pragma unroll
        for (int nf = 0; nf < 8; nf++)
            #pragma unroll
            for (int q = 0; q < 4; q++) s[nf][q] = 0.f;

        #pragma unroll
        for (int ks = 0; ks < 4; ks++) {
            uint32_t qh4[4], kk[4][4];
            uint32_t qoff = (uint32_t)(a_r * SR2 + a_c + ks * 16) * 2;
            ldsm_x4(qh4, sbase + qoff);
            #pragma unroll
            for (int nf2 = 0; nf2 < 4; nf2++) {
                uint32_t off = (uint32_t)((b_r + nf2 * 16) * SR2 + b_c + ks * 16) * 2;
                ldsm_x4(kk[nf2], stC + 0 * KBUF * 2 + off);
            }
            #pragma unroll
            for (int nf = 0; nf < 8; nf++)
                mma_f16(s[nf], qh4, &kk[nf >> 1][(nf & 1) * 2]);
        }

        // ---- p = exp2(s*scale + msk); accumulate l ----
        #pragma unroll
        for (int nf = 0; nf < 8; nf++) {
            float ma = ms[cur][nf * 8 + cq];
            float mb = ms[cur][nf * 8 + cq + 1];
            s[nf][0] = exp2f(fmaf(s[nf][0], 0.125f * LOG2E, ma));
            s[nf][1] = exp2f(fmaf(s[nf][1], 0.125f * LOG2E, mb));
            s[nf][2] = exp2f(fmaf(s[nf][2], 0.125f * LOG2E, ma));
            s[nf][3] = exp2f(fmaf(s[nf][3], 0.125f * LOG2E, mb));
            l0 += s[nf][0] + s[nf][1];
            l1 += s[nf][2] + s[nf][3];
        }

        // ---- repack P -> A-fragments (single fp16) ----
        uint32_t ph[4][4];
        #pragma unroll
        for (int kf = 0; kf < 4; kf++) {
            ph[kf][0] = pack_h2(s[2*kf][0],   s[2*kf][1]);
            ph[kf][1] = pack_h2(s[2*kf][2],   s[2*kf][3]);
            ph[kf][2] = pack_h2(s[2*kf+1][0], s[2*kf+1][1]);
            ph[kf][3] = pack_h2(s[2*kf+1][2], s[2*kf+1][3]);
        }

        // ---- O += P V ----
        #pragma unroll
        for (int ks = 0; ks < 4; ks++) {
            uint32_t vv[4][4];
            #pragma unroll
            for (int nf2 = 0; nf2 < 4; nf2++) {
                uint32_t off = (uint32_t)((ks * 16 + v_r) * SR2 + nf2 * 16 + v_c) * 2;
                ldsm_x4_t(vv[nf2], stC + 1 * KBUF * 2 + off);
            }
            #pragma unroll
            for (int nf = 0; nf < 8; nf++)
                mma_f16(o[nf], ph[ks], &vv[nf >> 1][(nf & 1) * 2]);
        }
        __syncthreads();
    }

    // ---- finalize ----
    l0 += __shfl_xor_sync(0xffffffffu, l0, 1);
    l0 += __shfl_xor_sync(0xffffffffu, l0, 2);
    l1 += __shfl_xor_sync(0xffffffffu, l1, 1);
    l1 += __shfl_xor_sync(0xffffffffu, l1, 2);
    float i0 = 1.f / l0, i1 = 1.f / l1;
    const int r0 = lane >> 2;
    const size_t mrow = (size_t)(b * MS + q0 + wid * 16 + r0);
    #pragma unroll
    for (int nf = 0; nf < 8; nf++) {
        int d = h * 64 + nf * 8 + cq;
        *(uint32_t*)(ctx + mrow * MD + d)       = pack_h2(o[nf][0] * i0, o[nf][1] * i0);
        *(uint32_t*)(ctx + (mrow + 8) * MD + d) = pack_h2(o[nf][2] * i1, o[nf][3] * i1);
    }
}

// ---------------- launch ----------------
extern "C" void kernel_launch(void* const* d_in, const int* in_sizes, int n_in,
                              void* d_out, int out_size)
{
    const float* x    = (const float*)d_in[0];
    const float* mask = (const float*)d_in[1];
    const float* Wq   = (const float*)d_in[2];
    const float* bq   = (const float*)d_in[3];
    const float* Wk   = (const float*)d_in[4];
    const float* bk   = (const float*)d_in[5];
    const float* Wv   = (const float*)d_in[6];
    const float* bv   = (const float*)d_in[7];
    const float* Wo   = (const float*)d_in[8];
    const float* bo   = (const float*)d_in[9];
    float* out = (float*)d_out;

    __half *pxh, *pqh, *pkh, *pvh, *pch, *pwt;
    float* pmsk;
    cudaGetSymbolAddress((void**)&pxh,  g_xh);
    cudaGetSymbolAddress((void**)&pqh,  g_qh);
    cudaGetSymbolAddress((void**)&pkh,  g_kh);
    cudaGetSymbolAddress((void**)&pvh,  g_vh);
    cudaGetSymbolAddress((void**)&pch,  g_ch);
    cudaGetSymbolAddress((void**)&pwt,  g_wt);
    cudaGetSymbolAddress((void**)&pmsk, g_msk);

    cudaFuncSetAttribute(gemm_mma, cudaFuncAttributeMaxDynamicSharedMemorySize, SMEM_TOTAL);
    cudaFuncSetAttribute(attn_mma, cudaFuncAttributeMaxDynamicSharedMemorySize, ATT_SMEM);

    // 0) prep: x -> fp16; mask pre-scale; transpose+round weights to fp16
    cvt_h<<<(MM * MD / 4) / 256, 256>>>(x, pxh);
    scale_mask<<<(MB * MS) / 256, 256>>>(mask, pmsk);
    dim3 gt(MD / 32, MD / 32, 4);
    transpose_cvt<<<gt, dim3(32, 32)>>>(Wq, Wk, Wv, Wo, pwt);

    // 1) fused QKV projections -> fp16
    dim3 gqkv(MD / 128, MM / 128, 3);
    gemm_mma<<<gqkv, 256, SMEM_TOTAL>>>(pxh, pwt, bq, bk, bv, nullptr,
                                        pqh, pkh, pvh);

    // 2) flash attention -> ctx fp16
    dim3 gattn(MS / 128, MB * MNH);
    attn_mma<<<gattn, 256, ATT_SMEM>>>(pmsk, pch);

    // 3) O projection -> fp32 out
    dim3 go(MD / 128, MM / 128, 1);
    gemm_mma<<<go, 256, SMEM_TOTAL>>>(pch, pwt + 3 * (size_t)MD * MD,
                                      bo, bo, bo, out,
                                      nullptr, nullptr, nullptr);
}

// round 14
// speedup vs baseline: 1.4668x; 1.0589x over previous
#include <cuda_runtime.h>
#include <cuda_fp16.h>
#include <math.h>
#include <stdint.h>

// Problem dims
#define MB  4
#define MS  2048
#define MD  1024
#define MNH 16
#define MHD 64
#define MM  (MB * MS)   // 8192 rows

// ---------------- scratch (allocation-free: __device__ globals) ----------------
__device__ __half g_xh[MM * MD];
__device__ __half g_qh[MM * MD];
__device__ __half g_kh[MM * MD];
__device__ __half g_vh[MM * MD];
__device__ __half g_ch[MM * MD];
__device__ __half g_wt[4 * MD * MD];   // W^T per matrix: [N,K] K-major, fp16
__device__ float  g_msk[MB * MS];      // mask * log2(e)

// ======================= mma.sync helpers (sm_80+, no 'a'-gate) ===============
__device__ __forceinline__ uint32_t smem_to_u32(const void* p) {
    uint32_t a;
    asm("{ .reg .u64 t; cvta.to.shared.u64 t, %1; cvt.u32.u64 %0, t; }" : "=r"(a) : "l"(p));
    return a;
}

__device__ __forceinline__ void ldsm_x4(uint32_t* r, uint32_t addr) {
    asm volatile("ldmatrix.sync.aligned.m8n8.x4.shared.b16 {%0,%1,%2,%3}, [%4];"
                 : "=r"(r[0]), "=r"(r[1]), "=r"(r[2]), "=r"(r[3]) : "r"(addr));
}
__device__ __forceinline__ void ldsm_x4_t(uint32_t* r, uint32_t addr) {
    asm volatile("ldmatrix.sync.aligned.m8n8.x4.trans.shared.b16 {%0,%1,%2,%3}, [%4];"
                 : "=r"(r[0]), "=r"(r[1]), "=r"(r[2]), "=r"(r[3]) : "r"(addr));
}

__device__ __forceinline__ void mma_f16(float* d, const uint32_t* a, const uint32_t* b) {
    asm volatile(
        "mma.sync.aligned.m16n8k16.row.col.f32.f16.f16.f32 "
        "{%0,%1,%2,%3}, {%4,%5,%6,%7}, {%8,%9}, {%0,%1,%2,%3};"
        : "+f"(d[0]), "+f"(d[1]), "+f"(d[2]), "+f"(d[3])
        : "r"(a[0]), "r"(a[1]), "r"(a[2]), "r"(a[3]), "r"(b[0]), "r"(b[1]));
}

#define CP_ASYNC16(dst, src) \
    asm volatile("cp.async.cg.shared.global [%0], [%1], 16;" :: "r"(dst), "l"(src))
#define CP_COMMIT() asm volatile("cp.async.commit_group;")
#define CP_WAIT0()  asm volatile("cp.async.wait_group 0;")
#define CP_WAIT1()  asm volatile("cp.async.wait_group 1;")

__device__ __forceinline__ uint32_t pack_h2(float a, float b) {
    __half2 t(__float2half_rn(a), __float2half_rn(b));
    return *(uint32_t*)&t;
}

#define LOG2E 1.4426950408889634f

// ======================= prep kernels =======================
__global__ __launch_bounds__(256)
void cvt_h(const float* __restrict__ x, __half* __restrict__ h)
{
    int i = blockIdx.x * blockDim.x + threadIdx.x;
    float4 v = ((const float4*)x)[i];
    uint32_t* H = (uint32_t*)h;
    H[2*i]   = pack_h2(v.x, v.y);
    H[2*i+1] = pack_h2(v.z, v.w);
}

__global__ __launch_bounds__(256)
void scale_mask(const float* __restrict__ mask, float* __restrict__ msk)
{
    int i = blockIdx.x * blockDim.x + threadIdx.x;
    msk[i] = mask[i] * LOG2E;
}

__global__ __launch_bounds__(1024)
void transpose_cvt(const float* __restrict__ W0, const float* __restrict__ W1,
                   const float* __restrict__ W2, const float* __restrict__ W3,
                   __half* __restrict__ wt)
{
    __shared__ float t[32][33];
    int z = blockIdx.z;
    const float* src = (z == 0) ? W0 : (z == 1) ? W1 : (z == 2) ? W2 : W3;
    int k = blockIdx.y * 32 + threadIdx.y;
    int n = blockIdx.x * 32 + threadIdx.x;
    t[threadIdx.y][threadIdx.x] = src[k * MD + n];
    __syncthreads();
    int nn = blockIdx.x * 32 + threadIdx.y;
    int kk = blockIdx.y * 32 + threadIdx.x;
    wt[(size_t)z * MD * MD + (size_t)nn * MD + kk] = __float2half_rn(t[threadIdx.x][threadIdx.y]);
}

// ======================= mma.sync GEMM: fp16, 3-stage cp.async ================
// C = A @ W + bias. 128x128 tile, BK=32, 3-stage cp.async pipeline with
// wait_group 1 (copy of chunk ch+2 overlaps compute of chunk ch).
#define GBK 32
#define NCHK (MD / GBK)        // 32
#define SROW 40                // 32 + 8 pad
#define BUF_E (128 * SROW)     // 5120 halfs per stage buffer
#define GST 3                  // pipeline stages
#define SMEM_TOTAL (2 * GST * BUF_E * 2)   // 61440 bytes

__global__ __launch_bounds__(256, 2)
void gemm_mma(const __half* __restrict__ A, const __half* __restrict__ Bt,
              const float* __restrict__ b0, const float* __restrict__ b1,
              const float* __restrict__ b2,
              float* __restrict__ Cf,
              __half* __restrict__ H0, __half* __restrict__ H1,
              __half* __restrict__ H2)
{
    extern __shared__ __half smem[];
    const int tid  = threadIdx.x;
    const int wid  = tid >> 5;
    const int lane = tid & 31;
    const int wm   = wid & 3;
    const int wn   = wid >> 2;

    const int z = blockIdx.z;
    const float* bias = (z == 0) ? b0 : (z == 1) ? b1 : b2;
    __half* Hout = (z == 0) ? H0 : (z == 1) ? H1 : H2;
    const __half* Bh = Bt + (size_t)z * MD * MD;

    const int n0 = blockIdx.x * 128;
    const int m0 = blockIdx.y * 128;

    // cp.async geometry: 512 x 16B chunks per buffer, 2 per thread
    const int r0g = (tid + 0)   >> 2, c0g = ((tid + 0)   & 3) << 3;
    const int r1g = (tid + 256) >> 2, c1g = ((tid + 256) & 3) << 3;
    const size_t gA0 = (size_t)(m0 + r0g) * MD + c0g;
    const size_t gA1 = (size_t)(m0 + r1g) * MD + c1g;
    const size_t gB0 = (size_t)(n0 + r0g) * MD + c0g;
    const size_t gB1 = (size_t)(n0 + r1g) * MD + c1g;
    const uint32_t s0 = (uint32_t)(r0g * SROW + c0g) * 2;
    const uint32_t s1 = (uint32_t)(r1g * SROW + c1g) * 2;

    const uint32_t base_u32 = smem_to_u32(smem);
    // stage st: A at st*BUF_E*2, B at (GST + st)*BUF_E*2
    const int a_r = wm * 32 + (lane & 15);
    const int a_c = (lane >> 4) << 3;
    const int b_r = wn * 64 + ((lane >> 4) << 3) + (lane & 7);
    const int b_c = ((lane >> 3) & 1) << 3;

    float acc[2][8][4];
    #pragma unroll
    for (int i = 0; i < 2; i++)
        #pragma unroll
        for (int j = 0; j < 8; j++)
            #pragma unroll
            for (int q = 0; q < 4; q++) acc[i][j][q] = 0.f;

    // ---- prologue: issue chunks 0 and 1 into stages 0 and 1 ----
    #pragma unroll
    for (int p = 0; p < 2; p++) {
        const int kc = p * GBK;
        const uint32_t stA = base_u32 + (uint32_t)(p * BUF_E) * 2;
        const uint32_t stB = base_u32 + (uint32_t)((GST + p) * BUF_E) * 2;
        CP_ASYNC16(stA + s0, A + gA0 + kc);
        CP_ASYNC16(stA + s1, A + gA1 + kc);
        CP_ASYNC16(stB + s0, Bh + gB0 + kc);
        CP_ASYNC16(stB + s1, Bh + gB1 + kc);
        CP_COMMIT();
    }

    int st = 0;
    for (int ch = 0; ch < NCHK; ch++) {
        if (ch < NCHK - 1) CP_WAIT1(); else CP_WAIT0();
        __syncthreads();   // stage ch data visible; all warps done with stage being refilled

        if (ch + 2 < NCHK) {
            const int nst = (st + 2 >= GST) ? st + 2 - GST : st + 2;
            const int kc = (ch + 2) * GBK;
            const uint32_t stA = base_u32 + (uint32_t)(nst * BUF_E) * 2;
            const uint32_t stB = base_u32 + (uint32_t)((GST + nst) * BUF_E) * 2;
            CP_ASYNC16(stA + s0, A + gA0 + kc);
            CP_ASYNC16(stA + s1, A + gA1 + kc);
            CP_ASYNC16(stB + s0, Bh + gB0 + kc);
            CP_ASYNC16(stB + s1, Bh + gB1 + kc);
            CP_COMMIT();
        }

        const uint32_t stA = base_u32 + (uint32_t)(st * BUF_E) * 2;
        const uint32_t stB = base_u32 + (uint32_t)((GST + st) * BUF_E) * 2;
        #pragma unroll
        for (int ks = 0; ks < 2; ks++) {
            uint32_t ah[2][4], bb[4][4];
            const int kcol = ks * 16;
            #pragma unroll
            for (int mf = 0; mf < 2; mf++) {
                uint32_t off = (uint32_t)((a_r + mf * 16) * SROW + a_c + kcol) * 2;
                ldsm_x4(ah[mf], stA + off);
            }
            #pragma unroll
            for (int nf2 = 0; nf2 < 4; nf2++) {
                uint32_t off = (uint32_t)((b_r + nf2 * 16) * SROW + b_c + kcol) * 2;
                ldsm_x4(bb[nf2], stB + off);
            }
            #pragma unroll
            for (int mf = 0; mf < 2; mf++)
                #pragma unroll
                for (int nf = 0; nf < 8; nf++)
                    mma_f16(acc[mf][nf], ah[mf], &bb[nf >> 1][(nf & 1) * 2]);
        }

        st = (st + 1 >= GST) ? 0 : st + 1;
    }

    const int tq = lane >> 2;
    const int tr = lane & 3;
    #pragma unroll
    for (int mf = 0; mf < 2; mf++) {
        #pragma unroll
        for (int nf = 0; nf < 8; nf++) {
            const int n = n0 + wn * 64 + nf * 8 + tr * 2;
            const float bv0 = bias[n], bv1 = bias[n + 1];
            const int m_top = m0 + wm * 32 + mf * 16 + tq;
            float v0 = acc[mf][nf][0] + bv0, v1 = acc[mf][nf][1] + bv1;
            float v2 = acc[mf][nf][2] + bv0, v3 = acc[mf][nf][3] + bv1;
            if (Hout) {
                *(uint32_t*)(Hout + (size_t)m_top * MD + n)       = pack_h2(v0, v1);
                *(uint32_t*)(Hout + (size_t)(m_top + 8) * MD + n) = pack_h2(v2, v3);
            } else {
                float2 w0, w1;
                w0.x = v0; w0.y = v1;
                w1.x = v2; w1.y = v3;
                *(float2*)(Cf + (size_t)m_top * MD + n)       = w0;
                *(float2*)(Cf + (size_t)(m_top + 8) * MD + n) = w1;
            }
        }
    }
}

// ======================= flash attention (unchanged from R13) =================
#define SR2 72
#define QBUF (128 * SR2)
#define KVT 64
#define KBUF (KVT * SR2)
#define ATT_SMEM ((QBUF + 4 * KBUF) * 2)   // 55296 bytes

__global__ __launch_bounds__(256, 2)
void attn_mma(const float* __restrict__ msk, __half* __restrict__ ctx)
{
    extern __shared__ __half sm[];   // [Q][stage][K|V]
    __shared__ float ms[2][KVT];

    const int tid  = threadIdx.x;
    const int wid  = tid >> 5;
    const int lane = tid & 31;
    const int bh   = blockIdx.y;
    const int b    = bh >> 4;
    const int h    = bh & 15;
    const int q0   = blockIdx.x * 128;

    const uint32_t sbase = smem_to_u32(sm);
    const uint32_t kvb   = sbase + (uint32_t)QBUF * 2;

    #pragma unroll
    for (int it = 0; it < 4; it++) {
        int i = tid + it * 256;
        int r = i >> 3, c = (i & 7) << 3;
        size_t g = (size_t)(b * MS + q0 + r) * MD + h * 64 + c;
        *(uint4*)&sm[r * SR2 + c] = *(const uint4*)(g_qh + g);
    }

    const int cr0 = (tid + 0)   >> 3, cc0 = ((tid + 0)   & 7) << 3;
    const int cr1 = (tid + 256) >> 3, cc1 = ((tid + 256) & 7) << 3;
    const uint32_t d0 = (uint32_t)(cr0 * SR2 + cc0) * 2;
    const uint32_t d1 = (uint32_t)(cr1 * SR2 + cc1) * 2;
    const uint32_t msb = smem_to_u32(ms);

    const int a_r = wid * 16 + (lane & 15);
    const int a_c = (lane >> 4) << 3;
    const int b_r = ((lane >> 4) << 3) + (lane & 7);
    const int b_c = ((lane >> 3) & 1) << 3;
    const int v_r = (((lane >> 3) & 1) << 3) + (lane & 7);
    const int v_c = (lane >> 4) << 3;
    const int cq  = (lane & 3) * 2;

    float l0 = 0.f, l1 = 0.f;
    float o[8][4];
    #pragma unroll
    for (int nf = 0; nf < 8; nf++)
        #pragma unroll
        for (int q = 0; q < 4; q++) o[nf][q] = 0.f;

    {
        size_t g0 = (size_t)(b * MS + cr0) * MD + h * 64 + cc0;
        size_t g1 = (size_t)(b * MS + cr1) * MD + h * 64 + cc1;
        CP_ASYNC16(kvb + 0 * KBUF * 2 + d0, g_kh + g0);
        CP_ASYNC16(kvb + 0 * KBUF * 2 + d1, g_kh + g1);
        CP_ASYNC16(kvb + 1 * KBUF * 2 + d0, g_vh + g0);
        CP_ASYNC16(kvb + 1 * KBUF * 2 + d1, g_vh + g1);
        if (tid < 16)
            CP_ASYNC16(msb + tid * 16, msk + b * MS + tid * 4);
        CP_COMMIT();
    }

    for (int kt = 0; kt < MS / KVT; kt++) {
        const int cur = kt & 1;
        CP_WAIT0();
        __syncthreads();

        if (kt < MS / KVT - 1) {
            const uint32_t stN = kvb + (uint32_t)((cur ^ 1) * 2 * KBUF) * 2;
            size_t g0 = (size_t)(b * MS + (kt + 1) * KVT + cr0) * MD + h * 64 + cc0;
            size_t g1 = (size_t)(b * MS + (kt + 1) * KVT + cr1) * MD + h * 64 + cc1;
            CP_ASYNC16(stN + 0 * KBUF * 2 + d0, g_kh + g0);
            CP_ASYNC16(stN + 0 * KBUF * 2 + d1, g_kh + g1);
            CP_ASYNC16(stN + 1 * KBUF * 2 + d0, g_vh + g0);
            CP_ASYNC16(stN + 1 * KBUF * 2 + d1, g_vh + g1);
            if (tid < 16)
                CP_ASYNC16(msb + (cur ^ 1) * 256 + tid * 16,
                           msk + b * MS + (kt + 1) * KVT + tid * 4);
            CP_COMMIT();
        }

        const uint32_t stC = kvb + (uint32_t)(cur * 2 * KBUF) * 2;

        float s[8][4];
        #pragma unroll
        for (int nf = 0; nf < 8; nf++)
            #pragma unroll
            for (int q = 0; q < 4; q++) s[nf][q] = 0.f;

        #pragma unroll
        for (int ks = 0; ks < 4; ks++) {
            uint32_t qh4[4], kk[4][4];
            uint32_t qoff = (uint32_t)(a_r * SR2 + a_c + ks * 16) * 2;
            ldsm_x4(qh4, sbase + qoff);
            #pragma unroll
            for (int nf2 = 0; nf2 < 4; nf2++) {
                uint32_t off = (uint32_t)((b_r + nf2 * 16) * SR2 + b_c + ks * 16) * 2;
                ldsm_x4(kk[nf2], stC + 0 * KBUF * 2 + off);
            }
            #pragma unroll
            for (int nf = 0; nf < 8; nf++)
                mma_f16(s[nf], qh4, &kk[nf >> 1][(nf & 1) * 2]);
        }

        #pragma unroll
        for (int nf = 0; nf < 8; nf++) {
            float ma = ms[cur][nf * 8 + cq];
            float mb = ms[cur][nf * 8 + cq + 1];
            s[nf][0] = exp2f(fmaf(s[nf][0], 0.125f * LOG2E, ma));
            s[nf][1] = exp2f(fmaf(s[nf][1], 0.125f * LOG2E, mb));
            s[nf][2] = exp2f(fmaf(s[nf][2], 0.125f * LOG2E, ma));
            s[nf][3] = exp2f(fmaf(s[nf][3], 0.125f * LOG2E, mb));
            l0 += s[nf][0] + s[nf][1];
            l1 += s[nf][2] + s[nf][3];
        }

        uint32_t ph[4][4];
        #pragma unroll
        for (int kf = 0; kf < 4; kf++) {
            ph[kf][0] = pack_h2(s[2*kf][0],   s[2*kf][1]);
            ph[kf][1] = pack_h2(s[2*kf][2],   s[2*kf][3]);
            ph[kf][2] = pack_h2(s[2*kf+1][0], s[2*kf+1][1]);
            ph[kf][3] = pack_h2(s[2*kf+1][2], s[2*kf+1][3]);
        }

        #pragma unroll
        for (int ks = 0; ks < 4; ks++) {
            uint32_t vv[4][4];
            #pragma unroll
            for (int nf2 = 0; nf2 < 4; nf2++) {
                uint32_t off = (uint32_t)((ks * 16 + v_r) * SR2 + nf2 * 16 + v_c) * 2;
                ldsm_x4_t(vv[nf2], stC + 1 * KBUF * 2 + off);
            }
            #pragma unroll
            for (int nf = 0; nf < 8; nf++)
                mma_f16(o[nf], ph[ks], &vv[nf >> 1][(nf & 1) * 2]);
        }
        __syncthreads();
    }

    l0 += __shfl_xor_sync(0xffffffffu, l0, 1);
    l0 += __shfl_xor_sync(0xffffffffu, l0, 2);
    l1 += __shfl_xor_sync(0xffffffffu, l1, 1);
    l1 += __shfl_xor_sync(0xffffffffu, l1, 2);
    float i0 = 1.f / l0, i1 = 1.f / l1;
    const int r0 = lane >> 2;
    const size_t mrow = (size_t)(b * MS + q0 + wid * 16 + r0);
    #pragma unroll
    for (int nf = 0; nf < 8; nf++) {
        int d = h * 64 + nf * 8 + cq;
        *(uint32_t*)(ctx + mrow * MD + d)       = pack_h2(o[nf][0] * i0, o[nf][1] * i0);
        *(uint32_t*)(ctx + (mrow + 8) * MD + d) = pack_h2(o[nf][2] * i1, o[nf][3] * i1);
    }
}

// ---------------- launch ----------------
extern "C" void kernel_launch(void* const* d_in, const int* in_sizes, int n_in,
                              void* d_out, int out_size)
{
    const float* x    = (const float*)d_in[0];
    const float* mask = (const float*)d_in[1];
    const float* Wq   = (const float*)d_in[2];
    const float* bq   = (const float*)d_in[3];
    const float* Wk   = (const float*)d_in[4];
    const float* bk   = (const float*)d_in[5];
    const float* Wv   = (const float*)d_in[6];
    const float* bv   = (const float*)d_in[7];
    const float* Wo   = (const float*)d_in[8];
    const float* bo   = (const float*)d_in[9];
    float* out = (float*)d_out;

    __half *pxh, *pqh, *pkh, *pvh, *pch, *pwt;
    float* pmsk;
    cudaGetSymbolAddress((void**)&pxh,  g_xh);
    cudaGetSymbolAddress((void**)&pqh,  g_qh);
    cudaGetSymbolAddress((void**)&pkh,  g_kh);
    cudaGetSymbolAddress((void**)&pvh,  g_vh);
    cudaGetSymbolAddress((void**)&pch,  g_ch);
    cudaGetSymbolAddress((void**)&pwt,  g_wt);
    cudaGetSymbolAddress((void**)&pmsk, g_msk);

    cudaFuncSetAttribute(gemm_mma, cudaFuncAttributeMaxDynamicSharedMemorySize, SMEM_TOTAL);
    cudaFuncSetAttribute(attn_mma, cudaFuncAttributeMaxDynamicSharedMemorySize, ATT_SMEM);

    // 0) prep: x -> fp16; mask pre-scale; transpose+round weights to fp16
    cvt_h<<<(MM * MD / 4) / 256, 256>>>(x, pxh);
    scale_mask<<<(MB * MS) / 256, 256>>>(mask, pmsk);
    dim3 gt(MD / 32, MD / 32, 4);
    transpose_cvt<<<gt, dim3(32, 32)>>>(Wq, Wk, Wv, Wo, pwt);

    // 1) fused QKV projections -> fp16
    dim3 gqkv(MD / 128, MM / 128, 3);
    gemm_mma<<<gqkv, 256, SMEM_TOTAL>>>(pxh, pwt, bq, bk, bv, nullptr,
                                        pqh, pkh, pvh);

    // 2) flash attention -> ctx fp16
    dim3 gattn(MS / 128, MB * MNH);
    attn_mma<<<gattn, 256, ATT_SMEM>>>(pmsk, pch);

    // 3) O projection -> fp32 out
    dim3 go(MD / 128, MM / 128, 1);
    gemm_mma<<<go, 256, SMEM_TOTAL>>>(pch, pwt + 3 * (size_t)MD * MD,
                                      bo, bo, bo, out,
                                      nullptr, nullptr, nullptr);
}

// round 15
// speedup vs baseline: 1.4872x; 1.0139x over previous
#include <cuda_runtime.h>
#include <cuda_fp16.h>
#include <math.h>
#include <stdint.h>

// Problem dims
#define MB  4
#define MS  2048
#define MD  1024
#define MNH 16
#define MHD 64
#define MM  (MB * MS)   // 8192 rows

// ---------------- scratch (allocation-free: __device__ globals) ----------------
__device__ __half g_xh[MM * MD];
__device__ __half g_qh[MM * MD];
__device__ __half g_kh[MM * MD];
__device__ __half g_vh[MM * MD];
__device__ __half g_ch[MM * MD];
__device__ __half g_wt[4 * MD * MD];   // W^T per matrix: [N,K] K-major, fp16
__device__ float  g_msk[MB * MS];      // mask * log2(e)

// ======================= mma.sync helpers (sm_80+, no 'a'-gate) ===============
__device__ __forceinline__ uint32_t smem_to_u32(const void* p) {
    uint32_t a;
    asm("{ .reg .u64 t; cvta.to.shared.u64 t, %1; cvt.u32.u64 %0, t; }" : "=r"(a) : "l"(p));
    return a;
}

__device__ __forceinline__ void ldsm_x4(uint32_t* r, uint32_t addr) {
    asm volatile("ldmatrix.sync.aligned.m8n8.x4.shared.b16 {%0,%1,%2,%3}, [%4];"
                 : "=r"(r[0]), "=r"(r[1]), "=r"(r[2]), "=r"(r[3]) : "r"(addr));
}
__device__ __forceinline__ void ldsm_x4_t(uint32_t* r, uint32_t addr) {
    asm volatile("ldmatrix.sync.aligned.m8n8.x4.trans.shared.b16 {%0,%1,%2,%3}, [%4];"
                 : "=r"(r[0]), "=r"(r[1]), "=r"(r[2]), "=r"(r[3]) : "r"(addr));
}

__device__ __forceinline__ void mma_f16(float* d, const uint32_t* a, const uint32_t* b) {
    asm volatile(
        "mma.sync.aligned.m16n8k16.row.col.f32.f16.f16.f32 "
        "{%0,%1,%2,%3}, {%4,%5,%6,%7}, {%8,%9}, {%0,%1,%2,%3};"
        : "+f"(d[0]), "+f"(d[1]), "+f"(d[2]), "+f"(d[3])
        : "r"(a[0]), "r"(a[1]), "r"(a[2]), "r"(a[3]), "r"(b[0]), "r"(b[1]));
}

#define CP_ASYNC16(dst, src) \
    asm volatile("cp.async.cg.shared.global [%0], [%1], 16;" :: "r"(dst), "l"(src))
#define CP_COMMIT() asm volatile("cp.async.commit_group;")
#define CP_WAIT0()  asm volatile("cp.async.wait_group 0;")
#define CP_WAIT2()  asm volatile("cp.async.wait_group 2;")

__device__ __forceinline__ uint32_t pack_h2(float a, float b) {
    __half2 t(__float2half_rn(a), __float2half_rn(b));
    return *(uint32_t*)&t;
}

__device__ __forceinline__ float ex2(float x) {
    float y;
    asm("ex2.approx.ftz.f32 %0, %1;" : "=f"(y) : "f"(x));
    return y;
}

#define LOG2E 1.4426950408889634f

// ======================= prep kernels =======================
__global__ __launch_bounds__(256)
void cvt_h(const float* __restrict__ x, __half* __restrict__ h)
{
    int i = blockIdx.x * blockDim.x + threadIdx.x;
    float4 v = ((const float4*)x)[i];
    uint32_t* H = (uint32_t*)h;
    H[2*i]   = pack_h2(v.x, v.y);
    H[2*i+1] = pack_h2(v.z, v.w);
}

__global__ __launch_bounds__(256)
void scale_mask(const float* __restrict__ mask, float* __restrict__ msk)
{
    int i = blockIdx.x * blockDim.x + threadIdx.x;
    msk[i] = mask[i] * LOG2E;
}

__global__ __launch_bounds__(1024)
void transpose_cvt(const float* __restrict__ W0, const float* __restrict__ W1,
                   const float* __restrict__ W2, const float* __restrict__ W3,
                   __half* __restrict__ wt)
{
    __shared__ float t[32][33];
    int z = blockIdx.z;
    const float* src = (z == 0) ? W0 : (z == 1) ? W1 : (z == 2) ? W2 : W3;
    int k = blockIdx.y * 32 + threadIdx.y;
    int n = blockIdx.x * 32 + threadIdx.x;
    t[threadIdx.y][threadIdx.x] = src[k * MD + n];
    __syncthreads();
    int nn = blockIdx.x * 32 + threadIdx.y;
    int kk = blockIdx.y * 32 + threadIdx.x;
    wt[(size_t)z * MD * MD + (size_t)nn * MD + kk] = __float2half_rn(t[threadIdx.x][threadIdx.y]);
}

// ======================= mma.sync GEMM: fp16, 4-stage cp.async ================
// C = A @ W + bias. 128x128 tile, BK=32, 4-stage cp.async pipeline with
// wait_group 2 (copy of chunk ch+3 overlaps compute of chunk ch).
#define GBK 32
#define NCHK (MD / GBK)        // 32
#define SROW 40                // 32 + 8 pad
#define BUF_E (128 * SROW)     // 5120 halfs per stage buffer
#define GST 4                  // pipeline stages
#define SMEM_TOTAL (2 * GST * BUF_E * 2)   // 81920 bytes

__global__ __launch_bounds__(256, 2)
void gemm_mma(const __half* __restrict__ A, const __half* __restrict__ Bt,
              const float* __restrict__ b0, const float* __restrict__ b1,
              const float* __restrict__ b2,
              float* __restrict__ Cf,
              __half* __restrict__ H0, __half* __restrict__ H1,
              __half* __restrict__ H2)
{
    extern __shared__ __half smem[];
    const int tid  = threadIdx.x;
    const int wid  = tid >> 5;
    const int lane = tid & 31;
    const int wm   = wid & 3;
    const int wn   = wid >> 2;

    const int z = blockIdx.z;
    const float* bias = (z == 0) ? b0 : (z == 1) ? b1 : b2;
    __half* Hout = (z == 0) ? H0 : (z == 1) ? H1 : H2;
    const __half* Bh = Bt + (size_t)z * MD * MD;

    const int n0 = blockIdx.x * 128;
    const int m0 = blockIdx.y * 128;

    // cp.async geometry: 512 x 16B chunks per buffer, 2 per thread
    const int r0g = (tid + 0)   >> 2, c0g = ((tid + 0)   & 3) << 3;
    const int r1g = (tid + 256) >> 2, c1g = ((tid + 256) & 3) << 3;
    const size_t gA0 = (size_t)(m0 + r0g) * MD + c0g;
    const size_t gA1 = (size_t)(m0 + r1g) * MD + c1g;
    const size_t gB0 = (size_t)(n0 + r0g) * MD + c0g;
    const size_t gB1 = (size_t)(n0 + r1g) * MD + c1g;
    const uint32_t s0 = (uint32_t)(r0g * SROW + c0g) * 2;
    const uint32_t s1 = (uint32_t)(r1g * SROW + c1g) * 2;

    const uint32_t base_u32 = smem_to_u32(smem);
    // stage st: A at st*BUF_E*2, B at (GST + st)*BUF_E*2
    const int a_r = wm * 32 + (lane & 15);
    const int a_c = (lane >> 4) << 3;
    const int b_r = wn * 64 + ((lane >> 4) << 3) + (lane & 7);
    const int b_c = ((lane >> 3) & 1) << 3;

    float acc[2][8][4];
    #pragma unroll
    for (int i = 0; i < 2; i++)
        #pragma unroll
        for (int j = 0; j < 8; j++)
            #pragma unroll
            for (int q = 0; q < 4; q++) acc[i][j][q] = 0.f;

    // ---- prologue: issue chunks 0..2 into stages 0..2 ----
    #pragma unroll
    for (int p = 0; p < GST - 1; p++) {
        const int kc = p * GBK;
        const uint32_t stA = base_u32 + (uint32_t)(p * BUF_E) * 2;
        const uint32_t stB = base_u32 + (uint32_t)((GST + p) * BUF_E) * 2;
        CP_ASYNC16(stA + s0, A + gA0 + kc);
        CP_ASYNC16(stA + s1, A + gA1 + kc);
        CP_ASYNC16(stB + s0, Bh + gB0 + kc);
        CP_ASYNC16(stB + s1, Bh + gB1 + kc);
        CP_COMMIT();
    }

    int st = 0;
    for (int ch = 0; ch < NCHK; ch++) {
        if (ch < NCHK - (GST - 1)) CP_WAIT2(); else CP_WAIT0();
        __syncthreads();   // stage ch data visible; all warps done with stage being refilled

        if (ch + GST - 1 < NCHK) {
            int nst = st + GST - 1;
            if (nst >= GST) nst -= GST;
            const int kc = (ch + GST - 1) * GBK;
            const uint32_t stA = base_u32 + (uint32_t)(nst * BUF_E) * 2;
            const uint32_t stB = base_u32 + (uint32_t)((GST + nst) * BUF_E) * 2;
            CP_ASYNC16(stA + s0, A + gA0 + kc);
            CP_ASYNC16(stA + s1, A + gA1 + kc);
            CP_ASYNC16(stB + s0, Bh + gB0 + kc);
            CP_ASYNC16(stB + s1, Bh + gB1 + kc);
            CP_COMMIT();
        }

        const uint32_t stA = base_u32 + (uint32_t)(st * BUF_E) * 2;
        const uint32_t stB = base_u32 + (uint32_t)((GST + st) * BUF_E) * 2;
        #pragma unroll
        for (int ks = 0; ks < 2; ks++) {
            uint32_t ah[2][4], bb[4][4];
            const int kcol = ks * 16;
            #pragma unroll
            for (int mf = 0; mf < 2; mf++) {
                uint32_t off = (uint32_t)((a_r + mf * 16) * SROW + a_c + kcol) * 2;
                ldsm_x4(ah[mf], stA + off);
            }
            #pragma unroll
            for (int nf2 = 0; nf2 < 4; nf2++) {
                uint32_t off = (uint32_t)((b_r + nf2 * 16) * SROW + b_c + kcol) * 2;
                ldsm_x4(bb[nf2], stB + off);
            }
            #pragma unroll
            for (int mf = 0; mf < 2; mf++)
                #pragma unroll
                for (int nf = 0; nf < 8; nf++)
                    mma_f16(acc[mf][nf], ah[mf], &bb[nf >> 1][(nf & 1) * 2]);
        }

        st = (st + 1 >= GST) ? 0 : st + 1;
    }

    const int tq = lane >> 2;
    const int tr = lane & 3;
    #pragma unroll
    for (int mf = 0; mf < 2; mf++) {
        #pragma unroll
        for (int nf = 0; nf < 8; nf++) {
            const int n = n0 + wn * 64 + nf * 8 + tr * 2;
            const float bv0 = bias[n], bv1 = bias[n + 1];
            const int m_top = m0 + wm * 32 + mf * 16 + tq;
            float v0 = acc[mf][nf][0] + bv0, v1 = acc[mf][nf][1] + bv1;
            float v2 = acc[mf][nf][2] + bv0, v3 = acc[mf][nf][3] + bv1;
            if (Hout) {
                *(uint32_t*)(Hout + (size_t)m_top * MD + n)       = pack_h2(v0, v1);
                *(uint32_t*)(Hout + (size_t)(m_top + 8) * MD + n) = pack_h2(v2, v3);
            } else {
                float2 w0, w1;
                w0.x = v0; w0.y = v1;
                w1.x = v2; w1.y = v3;
                *(float2*)(Cf + (size_t)m_top * MD + n)       = w0;
                *(float2*)(Cf + (size_t)(m_top + 8) * MD + n) = w1;
            }
        }
    }
}

// ======================= flash attention (ex2.approx softmax) =================
#define SR2 72
#define QBUF (128 * SR2)
#define KVT 64
#define KBUF (KVT * SR2)
#define ATT_SMEM ((QBUF + 4 * KBUF) * 2)   // 55296 bytes

__global__ __launch_bounds__(256, 2)
void attn_mma(const float* __restrict__ msk, __half* __restrict__ ctx)
{
    extern __shared__ __half sm[];   // [Q][stage][K|V]
    __shared__ float ms[2][KVT];

    const int tid  = threadIdx.x;
    const int wid  = tid >> 5;
    const int lane = tid & 31;
    const int bh   = blockIdx.y;
    const int b    = bh >> 4;
    const int h    = bh & 15;
    const int q0   = blockIdx.x * 128;

    const uint32_t sbase = smem_to_u32(sm);
    const uint32_t kvb   = sbase + (uint32_t)QBUF * 2;

    #pragma unroll
    for (int it = 0; it < 4; it++) {
        int i = tid + it * 256;
        int r = i >> 3, c = (i & 7) << 3;
        size_t g = (size_t)(b * MS + q0 + r) * MD + h * 64 + c;
        *(uint4*)&sm[r * SR2 + c] = *(const uint4*)(g_qh + g);
    }

    const int cr0 = (tid + 0)   >> 3, cc0 = ((tid + 0)   & 7) << 3;
    const int cr1 = (tid + 256) >> 3, cc1 = ((tid + 256) & 7) << 3;
    const uint32_t d0 = (uint32_t)(cr0 * SR2 + cc0) * 2;
    const uint32_t d1 = (uint32_t)(cr1 * SR2 + cc1) * 2;
    const uint32_t msb = smem_to_u32(ms);

    const int a_r = wid * 16 + (lane & 15);
    const int a_c = (lane >> 4) << 3;
    const int b_r = ((lane >> 4) << 3) + (lane & 7);
    const int b_c = ((lane >> 3) & 1) << 3;
    const int v_r = (((lane >> 3) & 1) << 3) + (lane & 7);
    const int v_c = (lane >> 4) << 3;
    const int cq  = (lane & 3) * 2;

    float l0 = 0.f, l1 = 0.f;
    float o[8][4];
    #pragma unroll
    for (int nf = 0; nf < 8; nf++)
        #pragma unroll
        for (int q = 0; q < 4; q++) o[nf][q] = 0.f;

    {
        size_t g0 = (size_t)(b * MS + cr0) * MD + h * 64 + cc0;
        size_t g1 = (size_t)(b * MS + cr1) * MD + h * 64 + cc1;
        CP_ASYNC16(kvb + 0 * KBUF * 2 + d0, g_kh + g0);
        CP_ASYNC16(kvb + 0 * KBUF * 2 + d1, g_kh + g1);
        CP_ASYNC16(kvb + 1 * KBUF * 2 + d0, g_vh + g0);
        CP_ASYNC16(kvb + 1 * KBUF * 2 + d1, g_vh + g1);
        if (tid < 16)
            CP_ASYNC16(msb + tid * 16, msk + b * MS + tid * 4);
        CP_COMMIT();
    }

    for (int kt = 0; kt < MS / KVT; kt++) {
        const int cur = kt & 1;
        CP_WAIT0();
        __syncthreads();

        if (kt < MS / KVT - 1) {
            const uint32_t stN = kvb + (uint32_t)((cur ^ 1) * 2 * KBUF) * 2;
            size_t g0 = (size_t)(b * MS + (kt + 1) * KVT + cr0) * MD + h * 64 + cc0;
            size_t g1 = (size_t)(b * MS + (kt + 1) * KVT + cr1) * MD + h * 64 + cc1;
            CP_ASYNC16(stN + 0 * KBUF * 2 + d0, g_kh + g0);
            CP_ASYNC16(stN + 0 * KBUF * 2 + d1, g_kh + g1);
            CP_ASYNC16(stN + 1 * KBUF * 2 + d0, g_vh + g0);
            CP_ASYNC16(stN + 1 * KBUF * 2 + d1, g_vh + g1);
            if (tid < 16)
                CP_ASYNC16(msb + (cur ^ 1) * 256 + tid * 16,
                           msk + b * MS + (kt + 1) * KVT + tid * 4);
            CP_COMMIT();
        }

        const uint32_t stC = kvb + (uint32_t)(cur * 2 * KBUF) * 2;

        float s[8][4];
        #pragma unroll
        for (int nf = 0; nf < 8; nf++)
            #pragma unroll
            for (int q = 0; q < 4; q++) s[nf][q] = 0.f;

        #pragma unroll
        for (int ks = 0; ks < 4; ks++) {
            uint32_t qh4[4], kk[4][4];
            uint32_t qoff = (uint32_t)(a_r * SR2 + a_c + ks * 16) * 2;
            ldsm_x4(qh4, sbase + qoff);
            #pragma unroll
            for (int nf2 = 0; nf2 < 4; nf2++) {
                uint32_t off = (uint32_t)((b_r + nf2 * 16) * SR2 + b_c + ks * 16) * 2;
                ldsm_x4(kk[nf2], stC + 0 * KBUF * 2 + off);
            }
            #pragma unroll
            for (int nf = 0; nf < 8; nf++)
                mma_f16(s[nf], qh4, &kk[nf >> 1][(nf & 1) * 2]);
        }

        #pragma unroll
        for (int nf = 0; nf < 8; nf++) {
            float ma = ms[cur][nf * 8 + cq];
            float mb = ms[cur][nf * 8 + cq + 1];
            s[nf][0] = ex2(fmaf(s[nf][0], 0.125f * LOG2E, ma));
            s[nf][1] = ex2(fmaf(s[nf][1], 0.125f * LOG2E, mb));
            s[nf][2] = ex2(fmaf(s[nf][2], 0.125f * LOG2E, ma));
            s[nf][3] = ex2(fmaf(s[nf][3], 0.125f * LOG2E, mb));
            l0 += s[nf][0] + s[nf][1];
            l1 += s[nf][2] + s[nf][3];
        }

        uint32_t ph[4][4];
        #pragma unroll
        for (int kf = 0; kf < 4; kf++) {
            ph[kf][0] = pack_h2(s[2*kf][0],   s[2*kf][1]);
            ph[kf][1] = pack_h2(s[2*kf][2],   s[2*kf][3]);
            ph[kf][2] = pack_h2(s[2*kf+1][0], s[2*kf+1][1]);
            ph[kf][3] = pack_h2(s[2*kf+1][2], s[2*kf+1][3]);
        }

        #pragma unroll
        for (int ks = 0; ks < 4; ks++) {
            uint32_t vv[4][4];
            #pragma unroll
            for (int nf2 = 0; nf2 < 4; nf2++) {
                uint32_t off = (uint32_t)((ks * 16 + v_r) * SR2 + nf2 * 16 + v_c) * 2;
                ldsm_x4_t(vv[nf2], stC + 1 * KBUF * 2 + off);
            }
            #pragma unroll
            for (int nf = 0; nf < 8; nf++)
                mma_f16(o[nf], ph[ks], &vv[nf >> 1][(nf & 1) * 2]);
        }
        __syncthreads();
    }

    l0 += __shfl_xor_sync(0xffffffffu, l0, 1);
    l0 += __shfl_xor_sync(0xffffffffu, l0, 2);
    l1 += __shfl_xor_sync(0xffffffffu, l1, 1);
    l1 += __shfl_xor_sync(0xffffffffu, l1, 2);
    float i0 = 1.f / l0, i1 = 1.f / l1;
    const int r0 = lane >> 2;
    const size_t mrow = (size_t)(b * MS + q0 + wid * 16 + r0);
    #pragma unroll
    for (int nf = 0; nf < 8; nf++) {
        int d = h * 64 + nf * 8 + cq;
        *(uint32_t*)(ctx + mrow * MD + d)       = pack_h2(o[nf][0] * i0, o[nf][1] * i0);
        *(uint32_t*)(ctx + (mrow + 8) * MD + d) = pack_h2(o[nf][2] * i1, o[nf][3] * i1);
    }
}

// ---------------- launch ----------------
extern "C" void kernel_launch(void* const* d_in, const int* in_sizes, int n_in,
                              void* d_out, int out_size)
{
    const float* x    = (const float*)d_in[0];
    const float* mask = (const float*)d_in[1];
    const float* Wq   = (const float*)d_in[2];
    const float* bq   = (const float*)d_in[3];
    const float* Wk   = (const float*)d_in[4];
    const float* bk   = (const float*)d_in[5];
    const float* Wv   = (const float*)d_in[6];
    const float* bv   = (const float*)d_in[7];
    const float* Wo   = (const float*)d_in[8];
    const float* bo   = (const float*)d_in[9];
    float* out = (float*)d_out;

    __half *pxh, *pqh, *pkh, *pvh, *pch, *pwt;
    float* pmsk;
    cudaGetSymbolAddress((void**)&pxh,  g_xh);
    cudaGetSymbolAddress((void**)&pqh,  g_qh);
    cudaGetSymbolAddress((void**)&pkh,  g_kh);
    cudaGetSymbolAddress((void**)&pvh,  g_vh);
    cudaGetSymbolAddress((void**)&pch,  g_ch);
    cudaGetSymbolAddress((void**)&pwt,  g_wt);
    cudaGetSymbolAddress((void**)&pmsk, g_msk);

    cudaFuncSetAttribute(gemm_mma, cudaFuncAttributeMaxDynamicSharedMemorySize, SMEM_TOTAL);
    cudaFuncSetAttribute(attn_mma, cudaFuncAttributeMaxDynamicSharedMemorySize, ATT_SMEM);

    // 0) prep: x -> fp16; mask pre-scale; transpose+round weights to fp16
    cvt_h<<<(MM * MD / 4) / 256, 256>>>(x, pxh);
    scale_mask<<<(MB * MS) / 256, 256>>>(mask, pmsk);
    dim3 gt(MD / 32, MD / 32, 4);
    transpose_cvt<<<gt, dim3(32, 32)>>>(Wq, Wk, Wv, Wo, pwt);

    // 1) fused QKV projections -> fp16
    dim3 gqkv(MD / 128, MM / 128, 3);
    gemm_mma<<<gqkv, 256, SMEM_TOTAL>>>(pxh, pwt, bq, bk, bv, nullptr,
                                        pqh, pkh, pvh);

    // 2) flash attention -> ctx fp16
    dim3 gattn(MS / 128, MB * MNH);
    attn_mma<<<gattn, 256, ATT_SMEM>>>(pmsk, pch);

    // 3) O projection -> fp32 out
    dim3 go(MD / 128, MM / 128, 1);
    gemm_mma<<<go, 256, SMEM_TOTAL>>>(pch, pwt + 3 * (size_t)MD * MD,
                                      bo, bo, bo, out,
                                      nullptr, nullptr, nullptr);
}

// round 16
// speedup vs baseline: 1.5742x; 1.0585x over previous
#include <cuda_runtime.h>
#include <cuda_fp16.h>
#include <math.h>
#include <stdint.h>

// Problem dims
#define MB  4
#define MS  2048
#define MD  1024
#define MNH 16
#define MHD 64
#define MM  (MB * MS)   // 8192 rows

// ---------------- scratch (allocation-free: __device__ globals) ----------------
__device__ __half g_xh[MM * MD];
__device__ __half g_qh[MM * MD];
__device__ __half g_kh[MM * MD];
__device__ __half g_vh[MM * MD];
__device__ __half g_ch[MM * MD];
__device__ __half g_wt[4 * MD * MD];   // W^T per matrix: [N,K] K-major, fp16
__device__ float  g_msk[MB * MS];      // mask * log2(e)

// ======================= mma.sync helpers (sm_80+, no 'a'-gate) ===============
__device__ __forceinline__ uint32_t smem_to_u32(const void* p) {
    uint32_t a;
    asm("{ .reg .u64 t; cvta.to.shared.u64 t, %1; cvt.u32.u64 %0, t; }" : "=r"(a) : "l"(p));
    return a;
}

__device__ __forceinline__ void ldsm_x4(uint32_t* r, uint32_t addr) {
    asm volatile("ldmatrix.sync.aligned.m8n8.x4.shared.b16 {%0,%1,%2,%3}, [%4];"
                 : "=r"(r[0]), "=r"(r[1]), "=r"(r[2]), "=r"(r[3]) : "r"(addr));
}
__device__ __forceinline__ void ldsm_x4_t(uint32_t* r, uint32_t addr) {
    asm volatile("ldmatrix.sync.aligned.m8n8.x4.trans.shared.b16 {%0,%1,%2,%3}, [%4];"
                 : "=r"(r[0]), "=r"(r[1]), "=r"(r[2]), "=r"(r[3]) : "r"(addr));
}

__device__ __forceinline__ void mma_f16(float* d, const uint32_t* a, const uint32_t* b) {
    asm volatile(
        "mma.sync.aligned.m16n8k16.row.col.f32.f16.f16.f32 "
        "{%0,%1,%2,%3}, {%4,%5,%6,%7}, {%8,%9}, {%0,%1,%2,%3};"
        : "+f"(d[0]), "+f"(d[1]), "+f"(d[2]), "+f"(d[3])
        : "r"(a[0]), "r"(a[1]), "r"(a[2]), "r"(a[3]), "r"(b[0]), "r"(b[1]));
}

#define CP_ASYNC16(dst, src) \
    asm volatile("cp.async.cg.shared.global [%0], [%1], 16;" :: "r"(dst), "l"(src))
#define CP_COMMIT() asm volatile("cp.async.commit_group;")
#define CP_WAIT0()  asm volatile("cp.async.wait_group 0;")

__device__ __forceinline__ uint32_t pack_h2(float a, float b) {
    __half2 t(__float2half_rn(a), __float2half_rn(b));
    return *(uint32_t*)&t;
}

__device__ __forceinline__ float ex2(float x) {
    float y;
    asm("ex2.approx.ftz.f32 %0, %1;" : "=f"(y) : "f"(x));
    return y;
}

#define LOG2E 1.4426950408889634f

// ======================= prep kernels =======================
__global__ __launch_bounds__(256)
void cvt_h(const float* __restrict__ x, __half* __restrict__ h)
{
    int i = blockIdx.x * blockDim.x + threadIdx.x;
    float4 v = ((const float4*)x)[i];
    uint32_t* H = (uint32_t*)h;
    H[2*i]   = pack_h2(v.x, v.y);
    H[2*i+1] = pack_h2(v.z, v.w);
}

__global__ __launch_bounds__(256)
void scale_mask(const float* __restrict__ mask, float* __restrict__ msk)
{
    int i = blockIdx.x * blockDim.x + threadIdx.x;
    msk[i] = mask[i] * LOG2E;
}

__global__ __launch_bounds__(1024)
void transpose_cvt(const float* __restrict__ W0, const float* __restrict__ W1,
                   const float* __restrict__ W2, const float* __restrict__ W3,
                   __half* __restrict__ wt)
{
    __shared__ float t[32][33];
    int z = blockIdx.z;
    const float* src = (z == 0) ? W0 : (z == 1) ? W1 : (z == 2) ? W2 : W3;
    int k = blockIdx.y * 32 + threadIdx.y;
    int n = blockIdx.x * 32 + threadIdx.x;
    t[threadIdx.y][threadIdx.x] = src[k * MD + n];
    __syncthreads();
    int nn = blockIdx.x * 32 + threadIdx.y;
    int kk = blockIdx.y * 32 + threadIdx.x;
    wt[(size_t)z * MD * MD + (size_t)nn * MD + kk] = __float2half_rn(t[threadIdx.x][threadIdx.y]);
}

// ======================= mma.sync GEMM: fp16, BK=64, cp.async 2-stage =========
// C = A @ W + bias. 128x128 tile, BK=64 (16 chunks), cp.async double-buffered
// (no register prefetch -> no spill at the 128-reg cap).
#define GBK 64
#define NCHK (MD / GBK)        // 16
#define SROW 72                // 64 + 8 pad
#define BUF_E (128 * SROW)     // halfs per stage buffer
#define SMEM_TOTAL (4 * BUF_E * 2)   // A[2] + B[2], 73728 bytes

__global__ __launch_bounds__(256, 2)
void gemm_mma(const __half* __restrict__ A, const __half* __restrict__ Bt,
              const float* __restrict__ b0, const float* __restrict__ b1,
              const float* __restrict__ b2,
              float* __restrict__ Cf,
              __half* __restrict__ H0, __half* __restrict__ H1,
              __half* __restrict__ H2)
{
    extern __shared__ __half smem[];
    const int tid  = threadIdx.x;
    const int wid  = tid >> 5;
    const int lane = tid & 31;
    const int wm   = wid & 3;
    const int wn   = wid >> 2;

    const int z = blockIdx.z;
    const float* bias = (z == 0) ? b0 : (z == 1) ? b1 : b2;
    __half* Hout = (z == 0) ? H0 : (z == 1) ? H1 : H2;
    const __half* Bh = Bt + (size_t)z * MD * MD;

    const int n0 = blockIdx.x * 128;
    const int m0 = blockIdx.y * 128;

    // cp.async geometry: 1024 x 16B chunks per buffer, 4 per thread
    const int cr = tid >> 3;            // row 0..127 (+ j*32 below)
    const int cc = (tid & 7) << 3;      // col 0,8,..56
    const uint32_t base_u32 = smem_to_u32(smem);
    // stage st: A at st*BUF_E, B at (2+st)*BUF_E (elems)

    const int a_r = wm * 32 + (lane & 15);
    const int a_c = (lane >> 4) << 3;
    const int b_r = wn * 64 + ((lane >> 4) << 3) + (lane & 7);
    const int b_c = ((lane >> 3) & 1) << 3;

    float acc[2][8][4];
    #pragma unroll
    for (int i = 0; i < 2; i++)
        #pragma unroll
        for (int j = 0; j < 8; j++)
            #pragma unroll
            for (int q = 0; q < 4; q++) acc[i][j][q] = 0.f;

    // ---- prologue: chunk 0 into stage 0 ----
    #pragma unroll
    for (int j = 0; j < 4; j++) {
        int r = cr + j * 32;
        uint32_t so = (uint32_t)(r * SROW + cc) * 2;
        CP_ASYNC16(base_u32 + so, A + (size_t)(m0 + r) * MD + cc);
        CP_ASYNC16(base_u32 + (uint32_t)(2 * BUF_E) * 2 + so, Bh + (size_t)(n0 + r) * MD + cc);
    }
    CP_COMMIT();

    int st = 0;
    for (int ch = 0; ch < NCHK; ch++) {
        CP_WAIT0();
        __syncthreads();

        if (ch < NCHK - 1) {
            const int nst = st ^ 1;
            const int kc = (ch + 1) * GBK;
            const uint32_t stA = base_u32 + (uint32_t)(nst * BUF_E) * 2;
            const uint32_t stB = base_u32 + (uint32_t)((2 + nst) * BUF_E) * 2;
            #pragma unroll
            for (int j = 0; j < 4; j++) {
                int r = cr + j * 32;
                uint32_t so = (uint32_t)(r * SROW + cc) * 2;
                CP_ASYNC16(stA + so, A + (size_t)(m0 + r) * MD + cc + kc);
                CP_ASYNC16(stB + so, Bh + (size_t)(n0 + r) * MD + cc + kc);
            }
            CP_COMMIT();
        }

        const uint32_t stA = base_u32 + (uint32_t)(st * BUF_E) * 2;
        const uint32_t stB = base_u32 + (uint32_t)((2 + st) * BUF_E) * 2;
        #pragma unroll
        for (int ks = 0; ks < 4; ks++) {
            uint32_t ah[2][4], bb[4][4];
            const int kcol = ks * 16;
            #pragma unroll
            for (int mf = 0; mf < 2; mf++) {
                uint32_t off = (uint32_t)((a_r + mf * 16) * SROW + a_c + kcol) * 2;
                ldsm_x4(ah[mf], stA + off);
            }
            #pragma unroll
            for (int nf2 = 0; nf2 < 4; nf2++) {
                uint32_t off = (uint32_t)((b_r + nf2 * 16) * SROW + b_c + kcol) * 2;
                ldsm_x4(bb[nf2], stB + off);
            }
            #pragma unroll
            for (int mf = 0; mf < 2; mf++)
                #pragma unroll
                for (int nf = 0; nf < 8; nf++)
                    mma_f16(acc[mf][nf], ah[mf], &bb[nf >> 1][(nf & 1) * 2]);
        }

        st ^= 1;
    }

    const int tq = lane >> 2;
    const int tr = lane & 3;
    #pragma unroll
    for (int mf = 0; mf < 2; mf++) {
        #pragma unroll
        for (int nf = 0; nf < 8; nf++) {
            const int n = n0 + wn * 64 + nf * 8 + tr * 2;
            const float bv0 = bias[n], bv1 = bias[n + 1];
            const int m_top = m0 + wm * 32 + mf * 16 + tq;
            float v0 = acc[mf][nf][0] + bv0, v1 = acc[mf][nf][1] + bv1;
            float v2 = acc[mf][nf][2] + bv0, v3 = acc[mf][nf][3] + bv1;
            if (Hout) {
                *(uint32_t*)(Hout + (size_t)m_top * MD + n)       = pack_h2(v0, v1);
                *(uint32_t*)(Hout + (size_t)(m_top + 8) * MD + n) = pack_h2(v2, v3);
            } else {
                float2 w0, w1;
                w0.x = v0; w0.y = v1;
                w1.x = v2; w1.y = v3;
                *(float2*)(Cf + (size_t)m_top * MD + n)       = w0;
                *(float2*)(Cf + (size_t)(m_top + 8) * MD + n) = w1;
            }
        }
    }
}

// ======================= flash attention: KVT=128, two halves per barrier =====
#define SR2 72
#define QBUF (128 * SR2)
#define KVT 128
#define KBUF (KVT * SR2)
#define ATT_SMEM ((QBUF + 4 * KBUF) * 2)   // 92160 bytes
// Requires ATT_SMEM <= 113 KB for 2 CTAs/SM: 90 KB OK.

__global__ __launch_bounds__(256, 2)
void attn_mma(const float* __restrict__ msk, __half* __restrict__ ctx)
{
    extern __shared__ __half sm[];   // [Q][stage][K|V]
    __shared__ float ms[2][KVT];

    const int tid  = threadIdx.x;
    const int wid  = tid >> 5;
    const int lane = tid & 31;
    const int bh   = blockIdx.y;
    const int b    = bh >> 4;
    const int h    = bh & 15;
    const int q0   = blockIdx.x * 128;

    const uint32_t sbase = smem_to_u32(sm);
    const uint32_t kvb   = sbase + (uint32_t)QBUF * 2;

    // ---- load Q tile (128x64) into resident smem ----
    #pragma unroll
    for (int it = 0; it < 4; it++) {
        int i = tid + it * 256;
        int r = i >> 3, c = (i & 7) << 3;
        size_t g = (size_t)(b * MS + q0 + r) * MD + h * 64 + c;
        *(uint4*)&sm[r * SR2 + c] = *(const uint4*)(g_qh + g);
    }

    // cp.async geometry: 1024 chunks per buffer, 4 per thread
    const int cr = tid >> 3;
    const int cc = (tid & 7) << 3;
    const uint32_t msb = smem_to_u32(ms);

    const int a_r = wid * 16 + (lane & 15);
    const int a_c = (lane >> 4) << 3;
    const int b_r = ((lane >> 4) << 3) + (lane & 7);
    const int b_c = ((lane >> 3) & 1) << 3;
    const int v_r = (((lane >> 3) & 1) << 3) + (lane & 7);
    const int v_c = (lane >> 4) << 3;
    const int cq  = (lane & 3) * 2;

    float l0 = 0.f, l1 = 0.f;
    float o[8][4];
    #pragma unroll
    for (int nf = 0; nf < 8; nf++)
        #pragma unroll
        for (int q = 0; q < 4; q++) o[nf][q] = 0.f;

    // ---- prologue: tile 0 ----
    #pragma unroll
    for (int j = 0; j < 4; j++) {
        int r = cr + j * 32;
        uint32_t so = (uint32_t)(r * SR2 + cc) * 2;
        size_t g = (size_t)(b * MS + r) * MD + h * 64 + cc;
        CP_ASYNC16(kvb + so, g_kh + g);
        CP_ASYNC16(kvb + (uint32_t)(2 * KBUF) * 2 + so, g_vh + g);
    }
    if (tid < 32)
        CP_ASYNC16(msb + tid * 16, msk + b * MS + tid * 4);
    CP_COMMIT();

    for (int kt = 0; kt < MS / KVT; kt++) {
        const int cur = kt & 1;
        CP_WAIT0();
        __syncthreads();

        if (kt < MS / KVT - 1) {
            const int nst = cur ^ 1;
            const uint32_t stK = kvb + (uint32_t)(nst * KBUF) * 2;
            const uint32_t stV = kvb + (uint32_t)((2 + nst) * KBUF) * 2;
            #pragma unroll
            for (int j = 0; j < 4; j++) {
                int r = cr + j * 32;
                uint32_t so = (uint32_t)(r * SR2 + cc) * 2;
                size_t g = (size_t)(b * MS + (kt + 1) * KVT + r) * MD + h * 64 + cc;
                CP_ASYNC16(stK + so, g_kh + g);
                CP_ASYNC16(stV + so, g_vh + g);
            }
            if (tid < 32)
                CP_ASYNC16(msb + nst * 512 + tid * 16,
                           msk + b * MS + (kt + 1) * KVT + tid * 4);
            CP_COMMIT();
        }

        const uint32_t stK = kvb + (uint32_t)(cur * KBUF) * 2;
        const uint32_t stV = kvb + (uint32_t)((2 + cur) * KBUF) * 2;

        #pragma unroll
        for (int half = 0; half < 2; half++) {
            const int rb = half * 64;

            // ---- S = Q K^T ----
            float s[8][4];
            #pragma unroll
            for (int nf = 0; nf < 8; nf++)
                #pragma unroll
                for (int q = 0; q < 4; q++) s[nf][q] = 0.f;

            #pragma unroll
            for (int ks = 0; ks < 4; ks++) {
                uint32_t qh4[4], kk[4][4];
                uint32_t qoff = (uint32_t)(a_r * SR2 + a_c + ks * 16) * 2;
                ldsm_x4(qh4, sbase + qoff);
                #pragma unroll
                for (int nf2 = 0; nf2 < 4; nf2++) {
                    uint32_t off = (uint32_t)((rb + b_r + nf2 * 16) * SR2 + b_c + ks * 16) * 2;
                    ldsm_x4(kk[nf2], stK + off);
                }
                #pragma unroll
                for (int nf = 0; nf < 8; nf++)
                    mma_f16(s[nf], qh4, &kk[nf >> 1][(nf & 1) * 2]);
            }

            // ---- p = exp2(s*scale + msk); accumulate l ----
            #pragma unroll
            for (int nf = 0; nf < 8; nf++) {
                float ma = ms[cur][rb + nf * 8 + cq];
                float mb = ms[cur][rb + nf * 8 + cq + 1];
                s[nf][0] = ex2(fmaf(s[nf][0], 0.125f * LOG2E, ma));
                s[nf][1] = ex2(fmaf(s[nf][1], 0.125f * LOG2E, mb));
                s[nf][2] = ex2(fmaf(s[nf][2], 0.125f * LOG2E, ma));
                s[nf][3] = ex2(fmaf(s[nf][3], 0.125f * LOG2E, mb));
                l0 += s[nf][0] + s[nf][1];
                l1 += s[nf][2] + s[nf][3];
            }

            // ---- repack P -> A-fragments ----
            uint32_t ph[4][4];
            #pragma unroll
            for (int kf = 0; kf < 4; kf++) {
                ph[kf][0] = pack_h2(s[2*kf][0],   s[2*kf][1]);
                ph[kf][1] = pack_h2(s[2*kf][2],   s[2*kf][3]);
                ph[kf][2] = pack_h2(s[2*kf+1][0], s[2*kf+1][1]);
                ph[kf][3] = pack_h2(s[2*kf+1][2], s[2*kf+1][3]);
            }

            // ---- O += P V ----
            #pragma unroll
            for (int ks = 0; ks < 4; ks++) {
                uint32_t vv[4][4];
                #pragma unroll
                for (int nf2 = 0; nf2 < 4; nf2++) {
                    uint32_t off = (uint32_t)((rb + ks * 16 + v_r) * SR2 + nf2 * 16 + v_c) * 2;
                    ldsm_x4_t(vv[nf2], stV + off);
                }
                #pragma unroll
                for (int nf = 0; nf < 8; nf++)
                    mma_f16(o[nf], ph[ks], &vv[nf >> 1][(nf & 1) * 2]);
            }
        }
        __syncthreads();
    }

    // ---- finalize ----
    l0 += __shfl_xor_sync(0xffffffffu, l0, 1);
    l0 += __shfl_xor_sync(0xffffffffu, l0, 2);
    l1 += __shfl_xor_sync(0xffffffffu, l1, 1);
    l1 += __shfl_xor_sync(0xffffffffu, l1, 2);
    float i0 = 1.f / l0, i1 = 1.f / l1;
    const int r0 = lane >> 2;
    const size_t mrow = (size_t)(b * MS + q0 + wid * 16 + r0);
    #pragma unroll
    for (int nf = 0; nf < 8; nf++) {
        int d = h * 64 + nf * 8 + cq;
        *(uint32_t*)(ctx + mrow * MD + d)       = pack_h2(o[nf][0] * i0, o[nf][1] * i0);
        *(uint32_t*)(ctx + (mrow + 8) * MD + d) = pack_h2(o[nf][2] * i1, o[nf][3] * i1);
    }
}

// ---------------- launch ----------------
extern "C" void kernel_launch(void* const* d_in, const int* in_sizes, int n_in,
                              void* d_out, int out_size)
{
    const float* x    = (const float*)d_in[0];
    const float* mask = (const float*)d_in[1];
    const float* Wq   = (const float*)d_in[2];
    const float* bq   = (const float*)d_in[3];
    const float* Wk   = (const float*)d_in[4];
    const float* bk   = (const float*)d_in[5];
    const float* Wv   = (const float*)d_in[6];
    const float* bv   = (const float*)d_in[7];
    const float* Wo   = (const float*)d_in[8];
    const float* bo   = (const float*)d_in[9];
    float* out = (float*)d_out;

    __half *pxh, *pqh, *pkh, *pvh, *pch, *pwt;
    float* pmsk;
    cudaGetSymbolAddress((void**)&pxh,  g_xh);
    cudaGetSymbolAddress((void**)&pqh,  g_qh);
    cudaGetSymbolAddress((void**)&pkh,  g_kh);
    cudaGetSymbolAddress((void**)&pvh,  g_vh);
    cudaGetSymbolAddress((void**)&pch,  g_ch);
    cudaGetSymbolAddress((void**)&pwt,  g_wt);
    cudaGetSymbolAddress((void**)&pmsk, g_msk);

    cudaFuncSetAttribute(gemm_mma, cudaFuncAttributeMaxDynamicSharedMemorySize, SMEM_TOTAL);
    cudaFuncSetAttribute(attn_mma, cudaFuncAttributeMaxDynamicSharedMemorySize, ATT_SMEM);

    // 0) prep: x -> fp16; mask pre-scale; transpose+round weights to fp16
    cvt_h<<<(MM * MD / 4) / 256, 256>>>(x, pxh);
    scale_mask<<<(MB * MS) / 256, 256>>>(mask, pmsk);
    dim3 gt(MD / 32, MD / 32, 4);
    transpose_cvt<<<gt, dim3(32, 32)>>>(Wq, Wk, Wv, Wo, pwt);

    // 1) fused QKV projections -> fp16
    dim3 gqkv(MD / 128, MM / 128, 3);
    gemm_mma<<<gqkv, 256, SMEM_TOTAL>>>(pxh, pwt, bq, bk, bv, nullptr,
                                        pqh, pkh, pvh);

    // 2) flash attention -> ctx fp16
    dim3 gattn(MS / 128, MB * MNH);
    attn_mma<<<gattn, 256, ATT_SMEM>>>(pmsk, pch);

    // 3) O projection -> fp32 out
    dim3 go(MD / 128, MM / 128, 1);
    gemm_mma<<<go, 256, SMEM_TOTAL>>>(pch, pwt + 3 * (size_t)MD * MD,
                                      bo, bo, bo, out,
                                      nullptr, nullptr, nullptr);
}